// round 6
// baseline (speedup 1.0000x reference)
#include <cuda_runtime.h>
#include <cuda_bf16.h>
#include <math.h>
#include <stdint.h>

#define Bn 16
#define Qn 4096
#define Gn 256
#define Cn 80
#define Ks 16   // shortlist size per column

// ---------------- device scratch ----------------
__device__ float g_tab[(size_t)Bn * Cn * Qn];          // [b][c][q]
__device__ unsigned char g_fgm[(size_t)Bn * Qn];
__device__ float g_cost[(size_t)Bn * Gn * Qn];         // [b][g][q]
__device__ int g_dk[(size_t)Bn * Gn];
__device__ int g_sidx[(size_t)Bn * Gn * Ks];           // lexicographic (cost,q) top-16 per column
__device__ unsigned g_mb[(size_t)Bn * Qn * 8];         // row bitmasks (256 bits)

// ---------------- helpers ----------------
__device__ __forceinline__ void warpMinPair(float &v, int &i) {
#pragma unroll
    for (int off = 16; off; off >>= 1) {
        float ov = __shfl_xor_sync(0xffffffffu, v, off);
        int   oi = __shfl_xor_sync(0xffffffffu, i, off);
        if (ov < v || (ov == v && oi < i)) { v = ov; i = oi; }
    }
}

// ---------------- K0: class cost table (fast log) ----------------
__global__ void tab_kernel(const float* __restrict__ logits) {
    int idx = blockIdx.x * 256 + threadIdx.x;   // over B*Q
    if (idx >= Bn * Qn) return;
    const float4* row = reinterpret_cast<const float4*>(logits + (size_t)idx * Cn);
    float* dst = g_tab + ((size_t)(idx / Qn) * Cn) * Qn + (idx % Qn);
#pragma unroll 4
    for (int c4 = 0; c4 < Cn / 4; c4++) {
        float4 xv = row[c4];
        float xs[4] = {xv.x, xv.y, xv.z, xv.w};
#pragma unroll
        for (int j = 0; j < 4; j++) {
            float x = xs[j];
            float pr = 1.0f / (1.0f + expf(-x));
            float neg = 0.75f * (pr * pr) * (-__logf(1.0f - pr + 1e-8f));
            float pos = 0.25f * ((1.0f - pr) * (1.0f - pr)) * (-__logf(pr + 1e-8f));
            dst[(size_t)(c4 * 4 + j) * Qn] = pos - neg;
        }
    }
}

// ---------------- K1: fg mask ----------------
__global__ void fg_kernel(const float* __restrict__ pred_boxes,
                          const float* __restrict__ gt_boxes) {
    __shared__ float s[Gn][8];
    int b = blockIdx.y;
    int q = blockIdx.x * 256 + threadIdx.x;
    int tid = threadIdx.x;
    {
        const float* gb = gt_boxes + ((size_t)b * Gn + tid) * 4;
        float gx0 = gb[0], gy0 = gb[1], gx1 = gb[2], gy1 = gb[3];
        float cx = (gx0 + gx1) * 0.5f, cy = (gy0 + gy1) * 0.5f;
        float gw = gx1 - gx0, gh = gy1 - gy0;
        float x0 = cx - gw * 0.5f, y0 = cy - gh * 0.5f;
        float x1 = cx + gw * 0.5f, y1 = cy + gh * 0.5f;
        float w = x1 - x0, h = y1 - y0;
        s[tid][0] = x0; s[tid][1] = y0; s[tid][2] = x1; s[tid][3] = y1;
        s[tid][4] = cx - 2.5f * w; s[tid][5] = cx + 2.5f * w;
        s[tid][6] = cy - 2.5f * h; s[tid][7] = cy + 2.5f * h;
    }
    __syncthreads();
    float4 p = reinterpret_cast<const float4*>(pred_boxes)[(size_t)b * Qn + q];
    float ax = (p.x + p.z) * 0.5f, ay = (p.y + p.w) * 0.5f;
    unsigned char fg = 0;
    for (int g = 0; g < Gn; g++) {
        bool ib = (ax > s[g][0]) && (ax < s[g][2]) && (ay > s[g][1]) && (ay < s[g][3]);
        bool ic = (ax > s[g][4]) && (ax < s[g][5]) && (ay > s[g][6]) && (ay < s[g][7]);
        if (ib || ic) { fg = 1; break; }
    }
    g_fgm[(size_t)b * Qn + q] = fg;
}

// ---------------- K2: full pairwise cost ----------------
__global__ void cost_kernel(const float* __restrict__ pred_boxes,
                            const float* __restrict__ pred_poses,
                            const int*   __restrict__ labels,
                            const float* __restrict__ gt_boxes,
                            const float* __restrict__ gt_t,
                            const float* __restrict__ gt_r,
                            const float* __restrict__ isz,
                            const float* __restrict__ iszt) {
    int q = blockIdx.x * 256 + threadIdx.x;
    int g = blockIdx.y;
    int b = blockIdx.z;

    const float* gb = gt_boxes + ((size_t)b * Gn + g) * 4;
    float gx0 = gb[0], gy0 = gb[1], gx1 = gb[2], gy1 = gb[3];
    const float* t3 = gt_t + ((size_t)b * Gn + g) * 3;
    const float* r3 = gt_r + ((size_t)b * Gn + g) * 3;
    int lab = labels[b * Gn + g];
    const float* is  = isz + (size_t)b * 4;
    const float* ist = iszt + ((size_t)b * Gn + g) * 4;

    float4 p = reinterpret_cast<const float4*>(pred_boxes)[(size_t)b * Qn + q];
    const float* ps = pred_poses + ((size_t)b * Qn + q) * 6;

    float area1 = (p.z - p.x) * (p.w - p.y);
    float area2 = (gx1 - gx0) * (gy1 - gy0);
    float lx = fmaxf(p.x, gx0), ly = fmaxf(p.y, gy0);
    float rx = fminf(p.z, gx1), ry = fminf(p.w, gy1);
    float wx = fmaxf(rx - lx, 0.0f), wy = fmaxf(ry - ly, 0.0f);
    float inter = wx * wy;
    float uni = area1 + area2 - inter;
    float iou = inter / uni;
    float Lx = fminf(p.x, gx0), Ly = fminf(p.y, gy0);
    float Rx = fmaxf(p.z, gx1), Ry = fmaxf(p.w, gy1);
    float ew = fmaxf(Rx - Lx, 0.0f), eh = fmaxf(Ry - Ly, 0.0f);
    float areaE = ew * eh;
    float giou = iou - (areaE - uni) / areaE;

    float cb = fabsf(p.x / is[0] - gx0 / ist[0])
             + fabsf(p.y / is[1] - gy0 / ist[1])
             + fabsf(p.z / is[2] - gx1 / ist[2])
             + fabsf(p.w / is[3] - gy1 / ist[3]);

    float cc = g_tab[((size_t)b * Cn + lab) * Qn + q];

    float ct = fabsf(ps[0] - t3[0]) + fabsf(ps[1] - t3[1]) + fabsf(ps[2] - t3[2]);
    float cr = fabsf(ps[3] - r3[0]) + fabsf(ps[4] - r3[1]) + fabsf(ps[5] - r3[2]);

    float ax = (p.x + p.z) * 0.5f, ay = (p.y + p.w) * 0.5f;
    float gcx = (gx0 + gx1) * 0.5f, gcy = (gy0 + gy1) * 0.5f;
    float gw = gx1 - gx0, gh = gy1 - gy0;
    float x0 = gcx - gw * 0.5f, y0 = gcy - gh * 0.5f;
    float x1 = gcx + gw * 0.5f, y1 = gcy + gh * 0.5f;
    bool in_box = (ax > x0) && (ax < x1) && (ay > y0) && (ay < y1);
    float w = x1 - x0, h = y1 - y0;
    bool in_ctr = (ax > gcx - 2.5f * w) && (ax < gcx + 2.5f * w) &&
                  (ay > gcy - 2.5f * h) && (ay < gcy + 2.5f * h);
    bool both = in_box && in_ctr;

    float cost = 5.0f * cb + 2.0f * cc + 2.0f * (-giou)
               + 100.0f * (both ? 0.0f : 1.0f) + 1.0f * ct + 1.0f * cr;
    cost += g_fgm[(size_t)b * Qn + q] ? 0.0f : 10000.0f;

    g_cost[((size_t)b * Gn + g) * Qn + q] = cost;
}

// ---------------- K4: per-column dk + lexicographic cost top-16 ----------------
__global__ void topk_kernel(const float* __restrict__ pred_boxes,
                            const float* __restrict__ gt_boxes) {
    int warp = threadIdx.x >> 5, lane = threadIdx.x & 31;
    int g = blockIdx.x * 4 + warp;
    int b = blockIdx.y;
    const float4* pb = reinterpret_cast<const float4*>(pred_boxes) + (size_t)b * Qn;
    const float* gb = gt_boxes + ((size_t)b * Gn + g) * 4;
    float gx0 = gb[0], gy0 = gb[1], gx1 = gb[2], gy1 = gb[3];
    float area2 = (gx1 - gx0) * (gy1 - gy0);
    const float* col = g_cost + ((size_t)b * Gn + g) * Qn;

    float iv[5]; float cv[Ks]; int ci[Ks];
#pragma unroll
    for (int k = 0; k < 5; k++) iv[k] = -INFINITY;
#pragma unroll
    for (int k = 0; k < Ks; k++) { cv[k] = INFINITY; ci[k] = 0x7fffffff; }

    for (int q = lane; q < Qn; q += 32) {
        float4 p = pb[q];
        float a1 = (p.z - p.x) * (p.w - p.y);
        float lx = fmaxf(p.x, gx0), ly = fmaxf(p.y, gy0);
        float rx = fminf(p.z, gx1), ry = fminf(p.w, gy1);
        float wx = fmaxf(rx - lx, 0.0f), wy = fmaxf(ry - ly, 0.0f);
        float inter = wx * wy;
        float iou = inter / (a1 + area2 - inter);
        if (iou > iv[4]) {
            iv[4] = iou;
#pragma unroll
            for (int k = 4; k > 0; k--)
                if (iv[k] > iv[k - 1]) { float t = iv[k]; iv[k] = iv[k - 1]; iv[k - 1] = t; }
        }
        float c = col[q];
        if (c < cv[Ks - 1] || (c == cv[Ks - 1] && q < ci[Ks - 1])) {
            cv[Ks - 1] = c; ci[Ks - 1] = q;
#pragma unroll
            for (int k = Ks - 1; k > 0; k--)
                if (cv[k] < cv[k - 1] || (cv[k] == cv[k - 1] && ci[k] < ci[k - 1])) {
                    float tv = cv[k]; cv[k] = cv[k - 1]; cv[k - 1] = tv;
                    int ti = ci[k]; ci[k] = ci[k - 1]; ci[k - 1] = ti;
                }
        }
    }

    // iou top-5 sum -> dk
    int p5 = 0; float sum = 0.0f;
    for (int r = 0; r < 5; r++) {
        float cand = (p5 < 5) ? iv[p5] : -INFINITY;
        float m = cand;
#pragma unroll
        for (int off = 16; off; off >>= 1) m = fmaxf(m, __shfl_xor_sync(0xffffffffu, m, off));
        sum += m;
        unsigned ball = __ballot_sync(0xffffffffu, cand == m);
        if (lane == (__ffs(ball) - 1)) p5++;
    }
    int dk = (int)sum;
    if (dk < 1) dk = 1;
    if (dk > 5) dk = 5;
    if (lane == 0) g_dk[(size_t)b * Gn + g] = dk;

    // cost lexicographic top-16 merge + store
    int p2 = 0;
    for (int r = 0; r < Ks; r++) {
        float cand = (p2 < Ks) ? cv[p2] : INFINITY;
        int candi = (p2 < Ks) ? ci[p2] : 0x7fffffff;
        float mv = cand; int mi = candi;
        warpMinPair(mv, mi);
        unsigned ball = __ballot_sync(0xffffffffu, (cand == mv) && (candi == mi));
        if (lane == (__ffs(ball) - 1)) p2++;
        if (lane == 0) g_sidx[((size_t)b * Gn + g) * Ks + r] = mi;
    }
}

// ---------------- K5: matching ----------------
__device__ __forceinline__ void reset_row_sh(unsigned* mb, int* s_rcnt, int* s_col,
                                             int q, int r) {
#pragma unroll
    for (int w = 0; w < 8; w++) {
        unsigned bits = mb[q * 8 + w];
        unsigned keep = ((r >> 5) == w) ? (1u << (r & 31)) : 0u;
        unsigned clr = bits & ~keep;
        while (clr) {
            int gp = __ffs(clr) - 1; clr &= clr - 1;
            atomicSub(&s_col[w * 32 + gp], 1);
        }
        if (keep && !(bits & keep)) atomicAdd(&s_col[r], 1);
        mb[q * 8 + w] = keep;
    }
    s_rcnt[q] = 1;
}

__global__ void __launch_bounds__(1024, 1) match_kernel(float* __restrict__ out) {
    int b = blockIdx.x, tid = threadIdx.x;
    int wid = tid >> 5, lane = tid & 31;
    const float* Cb = g_cost + (size_t)b * Gn * Qn;
    unsigned* mb = g_mb + (size_t)b * Qn * 8;
    const int* sidx = g_sidx + (size_t)b * Gn * Ks;

    __shared__ int s_rcnt[Qn];                 // 16KB
    __shared__ unsigned short s_pen[Qn];       // 8KB
    __shared__ unsigned char s_rg8[Qn];        // 4KB (valid only for stale rows)
    __shared__ unsigned s_mat[Qn / 32];        // snapshot matched bitmap
    __shared__ unsigned s_stale[Qn / 32];
    __shared__ int s_col[Gn];
    __shared__ unsigned short s_un[Gn], s_fb[Gn];
    __shared__ unsigned short s_slist[1024];
    __shared__ unsigned short s_mlist[Qn];     // 8KB
    __shared__ int s_ucnt, s_fbcnt, s_conf, s_scnt, s_mcnt;

    for (int i = tid; i < Qn * 8; i += 1024) mb[i] = 0u;
    for (int i = tid; i < Qn; i += 1024) { s_rcnt[i] = 0; s_pen[i] = 0; }
    for (int i = tid; i < Qn / 32; i += 1024) s_stale[i] = 0u;
    if (tid < Gn) s_col[tid] = g_dk[b * Gn + tid];
    if (tid == 0) s_scnt = 0;
    __syncthreads();

    // initial matches: first dk entries of the shortlist
    if (tid < Gn) {
        int dk = s_col[tid];
        for (int j = 0; j < dk; j++) {
            int q = sidx[tid * Ks + j];
            atomicOr(&mb[q * 8 + (tid >> 5)], 1u << (tid & 31));
            atomicAdd(&s_rcnt[q], 1);
        }
    }
    __syncthreads();
    for (int q = tid; q < Qn; q += 1024)
        if (s_rcnt[q] > 1) {
            atomicOr(&s_stale[q >> 5], 1u << (q & 31));
            int k = atomicAdd(&s_scnt, 1);
            if (k < 1024) s_slist[k] = (unsigned short)q;
        }
    __syncthreads();
    // lazy rg for stale rows (raw-cost argmin over g, lowest-g tie)
    int ns = s_scnt; if (ns > 1024) ns = 1024;
    for (int s = wid; s < ns; s += 32) {
        int q = s_slist[s];
        float bv = INFINITY; int bg = 0;
        for (int g = lane; g < Gn; g += 32) {
            float v = Cb[(size_t)g * Qn + q];
            if (v < bv) { bv = v; bg = g; }
        }
        warpMinPair(bv, bg);
        if (lane == 0) s_rg8[q] = (unsigned char)bg;
    }
    __syncthreads();
    // pre-loop stale reset
    for (int q = tid; q < Qn; q += 1024)
        if ((s_stale[q >> 5] >> (q & 31)) & 1)
            reset_row_sh(mb, s_rcnt, s_col, q, s_rg8[q]);
    __syncthreads();

    for (int it = 0; it < Gn; it++) {
        if (tid == 0) { s_ucnt = 0; s_fbcnt = 0; s_conf = 0; }
        __syncthreads();
        if (tid < Gn && s_col[tid] == 0) {
            int k = atomicAdd(&s_ucnt, 1); s_un[k] = (unsigned short)tid;
        }
        __syncthreads();
        int nu = s_ucnt;
        if (nu == 0) break;
        // penalties + matched snapshot (iteration-start state)
        for (int q = tid; q < Qn; q += 1024) if (s_rcnt[q] > 0) s_pen[q]++;
        if (tid < Qn / 32) {
            unsigned wb = 0;
#pragma unroll 8
            for (int j = 0; j < 32; j++) if (s_rcnt[tid * 32 + j] > 0) wb |= 1u << j;
            s_mat[tid] = wb;
        }
        __syncthreads();
        // assignments via shortlist walk
        if (tid < nu) {
            int g = s_un[tid];
            int chosen = -1;
            for (int j = 0; j < Ks; j++) {
                int q = sidx[g * Ks + j];
                if (!((s_mat[q >> 5] >> (q & 31)) & 1)) { chosen = q; break; }
            }
            if (chosen >= 0) {
                atomicOr(&mb[chosen * 8 + (g >> 5)], 1u << (g & 31));
                atomicAdd(&s_rcnt[chosen], 1);
                s_col[g] = 1;
            } else {
                int k = atomicAdd(&s_fbcnt, 1); s_fb[k] = (unsigned short)g;
            }
        }
        __syncthreads();
        // exact fallback (shortlist exhausted)
        int nfb = s_fbcnt;
        for (int u = wid; u < nfb; u += 32) {
            int g = s_fb[u];
            const float* col = Cb + (size_t)g * Qn;
            float bv = INFINITY; int bi = 0;
            for (int q = lane; q < Qn; q += 32) {
                if (!((s_mat[q >> 5] >> (q & 31)) & 1)) {
                    float v = col[q];
                    if (v < bv) { bv = v; bi = q; }
                }
            }
            warpMinPair(bv, bi);
            if (bv == INFINITY) {   // degenerate: every row matched
                bv = INFINITY; bi = 0;
                for (int q = lane; q < Qn; q += 32) {
                    float v = col[q] + 100000.0f * (float)s_pen[q];
                    if (v < bv) { bv = v; bi = q; }
                }
                warpMinPair(bv, bi);
            }
            if (lane == 0) {
                atomicOr(&mb[bi * 8 + (g >> 5)], 1u << (g & 31));
                atomicAdd(&s_rcnt[bi], 1);
                s_col[g] = 1;
            }
        }
        __syncthreads();
        for (int q = tid; q < Qn; q += 1024)
            if (s_rcnt[q] > 1) { s_conf = 1; break; }
        __syncthreads();
        if (s_conf) {
            for (int q = tid; q < Qn; q += 1024)
                if ((s_stale[q >> 5] >> (q & 31)) & 1)
                    reset_row_sh(mb, s_rcnt, s_col, q, s_rg8[q]);
            __syncthreads();
        }
    }

    // ---------- outputs (float32) ----------
    if (tid == 0) s_mcnt = 0;
    __syncthreads();
    float* out_sel = out;
    float* out_gt  = out + Bn * Qn;
    float* out_mq  = out + 2 * Bn * Qn;
    for (int q = tid; q < Qn; q += 1024) {
        int r = s_rcnt[q];
        out_sel[(size_t)b * Qn + q] = (r > 0) ? 1.0f : 0.0f;
        if (r > 0) { int k = atomicAdd(&s_mcnt, 1); s_mlist[k] = (unsigned short)q; }
        int first = 0;
#pragma unroll
        for (int w = 7; w >= 0; w--) {
            unsigned bits = mb[q * 8 + w];
            if (bits) first = w * 32 + __ffs(bits) - 1;
        }
        out_gt[(size_t)b * Qn + q] = (float)first;
    }
    __syncthreads();
    int nm = s_mcnt;
    for (int g = wid; g < Gn; g += 32) {
        const float* col = Cb + (size_t)g * Qn;
        int wsel = g >> 5; unsigned bsel = 1u << (g & 31);
        float bv = INFINITY; int bi = 0;
        for (int j = lane; j < nm; j += 32) {
            int q = s_mlist[j];
            if (mb[q * 8 + wsel] & bsel) {
                float v = col[q];
                int p = s_pen[q];
                for (int k = 0; k < p; k++) v += 100000.0f;  // sequential fp accumulation
                if (v < bv || (v == bv && q < bi)) { bv = v; bi = q; }
            }
        }
        warpMinPair(bv, bi);
        if (lane == 0) out_mq[(size_t)b * Gn + g] = (float)bi;
    }
}

// ---------------- launch ----------------
extern "C" void kernel_launch(void* const* d_in, const int* in_sizes, int n_in,
                              void* d_out, int out_size) {
    const float* pred_logits = (const float*)d_in[0];
    const float* pred_boxes  = (const float*)d_in[1];
    const float* pred_poses  = (const float*)d_in[2];
    const int*   labels      = (const int*)  d_in[3];
    const float* gt_boxes    = (const float*)d_in[4];
    const float* gt_trans    = (const float*)d_in[5];
    const float* gt_rot      = (const float*)d_in[6];
    const float* isz         = (const float*)d_in[7];
    const float* iszt        = (const float*)d_in[8];
    float* out = (float*)d_out;

    tab_kernel<<<(Bn * Qn + 255) / 256, 256>>>(pred_logits);
    fg_kernel<<<dim3(Qn / 256, Bn), 256>>>(pred_boxes, gt_boxes);
    cost_kernel<<<dim3(Qn / 256, Gn, Bn), 256>>>(pred_boxes, pred_poses, labels,
                                                 gt_boxes, gt_trans, gt_rot, isz, iszt);
    topk_kernel<<<dim3(Gn / 4, Bn), 128>>>(pred_boxes, gt_boxes);
    match_kernel<<<Bn, 1024>>>(out);
}

// round 7
// speedup vs baseline: 1.7645x; 1.7645x over previous
#include <cuda_runtime.h>
#include <cuda_bf16.h>
#include <math.h>
#include <stdint.h>

#define Bn 16
#define Qn 4096
#define Gn 256
#define Cn 80
#define Ks 16   // shortlist size per column

// ---------------- device scratch ----------------
__device__ float g_tab[(size_t)Bn * Cn * Qn];          // [b][c][q]
__device__ unsigned char g_fgm[(size_t)Bn * Qn];
__device__ float g_cost[(size_t)Bn * Gn * Qn];         // [b][g][q]
__device__ int g_dk[(size_t)Bn * Gn];
__device__ int g_sidx[(size_t)Bn * Gn * Ks];           // lexicographic (cost,q) top-16 per column
__device__ unsigned g_mb[(size_t)Bn * Qn * 8];         // row bitmasks (256 bits)

// ---------------- helpers ----------------
__device__ __forceinline__ void warpMinPair(float &v, int &i) {
#pragma unroll
    for (int off = 16; off; off >>= 1) {
        float ov = __shfl_xor_sync(0xffffffffu, v, off);
        int   oi = __shfl_xor_sync(0xffffffffu, i, off);
        if (ov < v || (ov == v && oi < i)) { v = ov; i = oi; }
    }
}

// ---------------- K0: class cost table (fast log) ----------------
__global__ void tab_kernel(const float* __restrict__ logits) {
    int idx = blockIdx.x * 256 + threadIdx.x;   // over B*Q
    if (idx >= Bn * Qn) return;
    const float4* row = reinterpret_cast<const float4*>(logits + (size_t)idx * Cn);
    float* dst = g_tab + ((size_t)(idx / Qn) * Cn) * Qn + (idx % Qn);
#pragma unroll 4
    for (int c4 = 0; c4 < Cn / 4; c4++) {
        float4 xv = row[c4];
        float xs[4] = {xv.x, xv.y, xv.z, xv.w};
#pragma unroll
        for (int j = 0; j < 4; j++) {
            float x = xs[j];
            float pr = 1.0f / (1.0f + expf(-x));
            float neg = 0.75f * (pr * pr) * (-__logf(1.0f - pr + 1e-8f));
            float pos = 0.25f * ((1.0f - pr) * (1.0f - pr)) * (-__logf(pr + 1e-8f));
            dst[(size_t)(c4 * 4 + j) * Qn] = pos - neg;
        }
    }
}

// ---------------- K1: fg mask ----------------
__global__ void fg_kernel(const float* __restrict__ pred_boxes,
                          const float* __restrict__ gt_boxes) {
    __shared__ float s[Gn][8];
    int b = blockIdx.y;
    int q = blockIdx.x * 256 + threadIdx.x;
    int tid = threadIdx.x;
    {
        const float* gb = gt_boxes + ((size_t)b * Gn + tid) * 4;
        float gx0 = gb[0], gy0 = gb[1], gx1 = gb[2], gy1 = gb[3];
        float cx = (gx0 + gx1) * 0.5f, cy = (gy0 + gy1) * 0.5f;
        float gw = gx1 - gx0, gh = gy1 - gy0;
        float x0 = cx - gw * 0.5f, y0 = cy - gh * 0.5f;
        float x1 = cx + gw * 0.5f, y1 = cy + gh * 0.5f;
        float w = x1 - x0, h = y1 - y0;
        s[tid][0] = x0; s[tid][1] = y0; s[tid][2] = x1; s[tid][3] = y1;
        s[tid][4] = cx - 2.5f * w; s[tid][5] = cx + 2.5f * w;
        s[tid][6] = cy - 2.5f * h; s[tid][7] = cy + 2.5f * h;
    }
    __syncthreads();
    float4 p = reinterpret_cast<const float4*>(pred_boxes)[(size_t)b * Qn + q];
    float ax = (p.x + p.z) * 0.5f, ay = (p.y + p.w) * 0.5f;
    unsigned char fg = 0;
    for (int g = 0; g < Gn; g++) {
        bool ib = (ax > s[g][0]) && (ax < s[g][2]) && (ay > s[g][1]) && (ay < s[g][3]);
        bool ic = (ax > s[g][4]) && (ax < s[g][5]) && (ay > s[g][6]) && (ay < s[g][7]);
        if (ib || ic) { fg = 1; break; }
    }
    g_fgm[(size_t)b * Qn + q] = fg;
}

// ---------------- K2: full pairwise cost ----------------
__global__ void cost_kernel(const float* __restrict__ pred_boxes,
                            const float* __restrict__ pred_poses,
                            const int*   __restrict__ labels,
                            const float* __restrict__ gt_boxes,
                            const float* __restrict__ gt_t,
                            const float* __restrict__ gt_r,
                            const float* __restrict__ isz,
                            const float* __restrict__ iszt) {
    int q = blockIdx.x * 256 + threadIdx.x;
    int g = blockIdx.y;
    int b = blockIdx.z;

    const float* gb = gt_boxes + ((size_t)b * Gn + g) * 4;
    float gx0 = gb[0], gy0 = gb[1], gx1 = gb[2], gy1 = gb[3];
    const float* t3 = gt_t + ((size_t)b * Gn + g) * 3;
    const float* r3 = gt_r + ((size_t)b * Gn + g) * 3;
    int lab = labels[b * Gn + g];
    const float* is  = isz + (size_t)b * 4;
    const float* ist = iszt + ((size_t)b * Gn + g) * 4;

    float4 p = reinterpret_cast<const float4*>(pred_boxes)[(size_t)b * Qn + q];
    const float* ps = pred_poses + ((size_t)b * Qn + q) * 6;

    float area1 = (p.z - p.x) * (p.w - p.y);
    float area2 = (gx1 - gx0) * (gy1 - gy0);
    float lx = fmaxf(p.x, gx0), ly = fmaxf(p.y, gy0);
    float rx = fminf(p.z, gx1), ry = fminf(p.w, gy1);
    float wx = fmaxf(rx - lx, 0.0f), wy = fmaxf(ry - ly, 0.0f);
    float inter = wx * wy;
    float uni = area1 + area2 - inter;
    float iou = inter / uni;
    float Lx = fminf(p.x, gx0), Ly = fminf(p.y, gy0);
    float Rx = fmaxf(p.z, gx1), Ry = fmaxf(p.w, gy1);
    float ew = fmaxf(Rx - Lx, 0.0f), eh = fmaxf(Ry - Ly, 0.0f);
    float areaE = ew * eh;
    float giou = iou - (areaE - uni) / areaE;

    float cb = fabsf(p.x / is[0] - gx0 / ist[0])
             + fabsf(p.y / is[1] - gy0 / ist[1])
             + fabsf(p.z / is[2] - gx1 / ist[2])
             + fabsf(p.w / is[3] - gy1 / ist[3]);

    float cc = g_tab[((size_t)b * Cn + lab) * Qn + q];

    float ct = fabsf(ps[0] - t3[0]) + fabsf(ps[1] - t3[1]) + fabsf(ps[2] - t3[2]);
    float cr = fabsf(ps[3] - r3[0]) + fabsf(ps[4] - r3[1]) + fabsf(ps[5] - r3[2]);

    float ax = (p.x + p.z) * 0.5f, ay = (p.y + p.w) * 0.5f;
    float gcx = (gx0 + gx1) * 0.5f, gcy = (gy0 + gy1) * 0.5f;
    float gw = gx1 - gx0, gh = gy1 - gy0;
    float x0 = gcx - gw * 0.5f, y0 = gcy - gh * 0.5f;
    float x1 = gcx + gw * 0.5f, y1 = gcy + gh * 0.5f;
    bool in_box = (ax > x0) && (ax < x1) && (ay > y0) && (ay < y1);
    float w = x1 - x0, h = y1 - y0;
    bool in_ctr = (ax > gcx - 2.5f * w) && (ax < gcx + 2.5f * w) &&
                  (ay > gcy - 2.5f * h) && (ay < gcy + 2.5f * h);
    bool both = in_box && in_ctr;

    float cost = 5.0f * cb + 2.0f * cc + 2.0f * (-giou)
               + 100.0f * (both ? 0.0f : 1.0f) + 1.0f * ct + 1.0f * cr;
    cost += g_fgm[(size_t)b * Qn + q] ? 0.0f : 10000.0f;

    g_cost[((size_t)b * Gn + g) * Qn + q] = cost;
}

// ---------------- K3: per-column dk (iou top-5 sum), lean ----------------
__global__ void dk_kernel(const float* __restrict__ pred_boxes,
                          const float* __restrict__ gt_boxes) {
    int warp = threadIdx.x >> 5, lane = threadIdx.x & 31;
    int g = blockIdx.x * 4 + warp;
    int b = blockIdx.y;
    const float4* pb = reinterpret_cast<const float4*>(pred_boxes) + (size_t)b * Qn;
    const float* gb = gt_boxes + ((size_t)b * Gn + g) * 4;
    float gx0 = gb[0], gy0 = gb[1], gx1 = gb[2], gy1 = gb[3];
    float area2 = (gx1 - gx0) * (gy1 - gy0);

    float iv[5];
#pragma unroll
    for (int k = 0; k < 5; k++) iv[k] = -INFINITY;

    for (int q = lane; q < Qn; q += 32) {
        float4 p = pb[q];
        float a1 = (p.z - p.x) * (p.w - p.y);
        float lx = fmaxf(p.x, gx0), ly = fmaxf(p.y, gy0);
        float rx = fminf(p.z, gx1), ry = fminf(p.w, gy1);
        float wx = fmaxf(rx - lx, 0.0f), wy = fmaxf(ry - ly, 0.0f);
        float inter = wx * wy;
        float iou = inter / (a1 + area2 - inter);
        if (iou > iv[4]) {
            iv[4] = iou;
#pragma unroll
            for (int k = 4; k > 0; k--) {
                float lo = fminf(iv[k], iv[k - 1]);
                float hi = fmaxf(iv[k], iv[k - 1]);
                iv[k] = lo; iv[k - 1] = hi;
            }
        }
    }

    // iou top-5 sum across warp (descending extraction)
    int p5 = 0; float sum = 0.0f;
    for (int r = 0; r < 5; r++) {
        float cand = (p5 < 5) ? iv[p5] : -INFINITY;
        float m = cand;
#pragma unroll
        for (int off = 16; off; off >>= 1) m = fmaxf(m, __shfl_xor_sync(0xffffffffu, m, off));
        sum += m;
        unsigned ball = __ballot_sync(0xffffffffu, cand == m);
        if (lane == (__ffs(ball) - 1)) p5++;
    }
    int dk = (int)sum;
    if (dk < 1) dk = 1;
    if (dk > 5) dk = 5;
    if (lane == 0) g_dk[(size_t)b * Gn + g] = dk;
}

// ---------------- K4: per-column lexicographic cost top-16 (u64 keys) ----------------
__device__ __forceinline__ unsigned long long costKey(float v, int q) {
    unsigned bits = __float_as_uint(v);
    unsigned mk = (bits & 0x80000000u) ? ~bits : (bits ^ 0x80000000u);
    return ((unsigned long long)mk << 32) | (unsigned)q;
}

__global__ void short_kernel() {
    int warp = threadIdx.x >> 5, lane = threadIdx.x & 31;
    int col = blockIdx.x * 4 + warp;        // over Bn*Gn columns
    const float4* c4 = reinterpret_cast<const float4*>(g_cost + (size_t)col * Qn);

    unsigned long long t[Ks];
#pragma unroll
    for (int k = 0; k < Ks; k++) t[k] = ~0ull;

    for (int i = lane; i < Qn / 4; i += 32) {
        float4 v = c4[i];
        int q0 = i * 4;
#pragma unroll
        for (int j = 0; j < 4; j++) {
            float vv = (j == 0) ? v.x : (j == 1) ? v.y : (j == 2) ? v.z : v.w;
            unsigned long long key = costKey(vv, q0 + j);
            if (key < t[Ks - 1]) {
                t[Ks - 1] = key;
#pragma unroll
                for (int k = Ks - 1; k > 0; k--) {
                    unsigned long long a = t[k - 1], bb = t[k];
                    t[k - 1] = (a < bb) ? a : bb;
                    t[k]     = (a < bb) ? bb : a;
                }
            }
        }
    }

    // warp merge: 16 rounds of u64 min extraction (keys are unique: q embedded)
    int p = 0;
    int* dst = g_sidx + (size_t)col * Ks;
    for (int r = 0; r < Ks; r++) {
        unsigned long long cand = (p < Ks) ? t[p] : ~0ull;
        unsigned long long m = cand;
#pragma unroll
        for (int off = 16; off; off >>= 1) {
            unsigned long long o = __shfl_xor_sync(0xffffffffu, m, off);
            if (o < m) m = o;
        }
        if (cand == m) {  // exactly one lane
            p++;
            dst[r] = (int)(m & 0xffffffffu);
        }
    }
}

// ---------------- K5: matching ----------------
__device__ __forceinline__ void reset_row_sh(unsigned* mb, int* s_rcnt, int* s_col,
                                             int q, int r) {
#pragma unroll
    for (int w = 0; w < 8; w++) {
        unsigned bits = mb[q * 8 + w];
        unsigned keep = ((r >> 5) == w) ? (1u << (r & 31)) : 0u;
        unsigned clr = bits & ~keep;
        while (clr) {
            int gp = __ffs(clr) - 1; clr &= clr - 1;
            atomicSub(&s_col[w * 32 + gp], 1);
        }
        if (keep && !(bits & keep)) atomicAdd(&s_col[r], 1);
        mb[q * 8 + w] = keep;
    }
    s_rcnt[q] = 1;
}

__global__ void __launch_bounds__(1024, 1) match_kernel(float* __restrict__ out) {
    int b = blockIdx.x, tid = threadIdx.x;
    int wid = tid >> 5, lane = tid & 31;
    const float* Cb = g_cost + (size_t)b * Gn * Qn;
    unsigned* mb = g_mb + (size_t)b * Qn * 8;
    const int* sidx = g_sidx + (size_t)b * Gn * Ks;

    __shared__ int s_rcnt[Qn];
    __shared__ unsigned short s_pen[Qn];
    __shared__ unsigned char s_rg8[Qn];
    __shared__ unsigned s_mat[Qn / 32];
    __shared__ unsigned s_stale[Qn / 32];
    __shared__ int s_col[Gn];
    __shared__ unsigned short s_un[Gn], s_fb[Gn];
    __shared__ unsigned short s_slist[1024];
    __shared__ unsigned short s_mlist[Qn];
    __shared__ int s_ucnt, s_fbcnt, s_conf, s_scnt, s_mcnt;

    for (int i = tid; i < Qn * 8; i += 1024) mb[i] = 0u;
    for (int i = tid; i < Qn; i += 1024) { s_rcnt[i] = 0; s_pen[i] = 0; }
    for (int i = tid; i < Qn / 32; i += 1024) s_stale[i] = 0u;
    if (tid < Gn) s_col[tid] = g_dk[b * Gn + tid];
    if (tid == 0) s_scnt = 0;
    __syncthreads();

    // initial matches: first dk entries of the shortlist
    if (tid < Gn) {
        int dk = s_col[tid];
        for (int j = 0; j < dk; j++) {
            int q = sidx[tid * Ks + j];
            atomicOr(&mb[q * 8 + (tid >> 5)], 1u << (tid & 31));
            atomicAdd(&s_rcnt[q], 1);
        }
    }
    __syncthreads();
    for (int q = tid; q < Qn; q += 1024)
        if (s_rcnt[q] > 1) {
            atomicOr(&s_stale[q >> 5], 1u << (q & 31));
            int k = atomicAdd(&s_scnt, 1);
            if (k < 1024) s_slist[k] = (unsigned short)q;
        }
    __syncthreads();
    // lazy rg for stale rows (raw-cost argmin over g, lowest-g tie)
    int ns = s_scnt; if (ns > 1024) ns = 1024;
    for (int s = wid; s < ns; s += 32) {
        int q = s_slist[s];
        float bv = INFINITY; int bg = 0;
        for (int g = lane; g < Gn; g += 32) {
            float v = Cb[(size_t)g * Qn + q];
            if (v < bv) { bv = v; bg = g; }
        }
        warpMinPair(bv, bg);
        if (lane == 0) s_rg8[q] = (unsigned char)bg;
    }
    __syncthreads();
    // pre-loop stale reset
    for (int q = tid; q < Qn; q += 1024)
        if ((s_stale[q >> 5] >> (q & 31)) & 1)
            reset_row_sh(mb, s_rcnt, s_col, q, s_rg8[q]);
    __syncthreads();

    for (int it = 0; it < Gn; it++) {
        if (tid == 0) { s_ucnt = 0; s_fbcnt = 0; s_conf = 0; }
        __syncthreads();
        if (tid < Gn && s_col[tid] == 0) {
            int k = atomicAdd(&s_ucnt, 1); s_un[k] = (unsigned short)tid;
        }
        __syncthreads();
        int nu = s_ucnt;
        if (nu == 0) break;
        // penalties + matched snapshot (iteration-start state)
        for (int q = tid; q < Qn; q += 1024) if (s_rcnt[q] > 0) s_pen[q]++;
        if (tid < Qn / 32) {
            unsigned wb = 0;
#pragma unroll 8
            for (int j = 0; j < 32; j++) if (s_rcnt[tid * 32 + j] > 0) wb |= 1u << j;
            s_mat[tid] = wb;
        }
        __syncthreads();
        // assignments via shortlist walk
        if (tid < nu) {
            int g = s_un[tid];
            int chosen = -1;
            for (int j = 0; j < Ks; j++) {
                int q = sidx[g * Ks + j];
                if (!((s_mat[q >> 5] >> (q & 31)) & 1)) { chosen = q; break; }
            }
            if (chosen >= 0) {
                atomicOr(&mb[chosen * 8 + (g >> 5)], 1u << (g & 31));
                atomicAdd(&s_rcnt[chosen], 1);
                s_col[g] = 1;
            } else {
                int k = atomicAdd(&s_fbcnt, 1); s_fb[k] = (unsigned short)g;
            }
        }
        __syncthreads();
        // exact fallback (shortlist exhausted)
        int nfb = s_fbcnt;
        for (int u = wid; u < nfb; u += 32) {
            int g = s_fb[u];
            const float* col = Cb + (size_t)g * Qn;
            float bv = INFINITY; int bi = 0;
            for (int q = lane; q < Qn; q += 32) {
                if (!((s_mat[q >> 5] >> (q & 31)) & 1)) {
                    float v = col[q];
                    if (v < bv) { bv = v; bi = q; }
                }
            }
            warpMinPair(bv, bi);
            if (bv == INFINITY) {   // degenerate: every row matched
                bv = INFINITY; bi = 0;
                for (int q = lane; q < Qn; q += 32) {
                    float v = col[q] + 100000.0f * (float)s_pen[q];
                    if (v < bv) { bv = v; bi = q; }
                }
                warpMinPair(bv, bi);
            }
            if (lane == 0) {
                atomicOr(&mb[bi * 8 + (g >> 5)], 1u << (g & 31));
                atomicAdd(&s_rcnt[bi], 1);
                s_col[g] = 1;
            }
        }
        __syncthreads();
        for (int q = tid; q < Qn; q += 1024)
            if (s_rcnt[q] > 1) { s_conf = 1; break; }
        __syncthreads();
        if (s_conf) {
            for (int q = tid; q < Qn; q += 1024)
                if ((s_stale[q >> 5] >> (q & 31)) & 1)
                    reset_row_sh(mb, s_rcnt, s_col, q, s_rg8[q]);
            __syncthreads();
        }
    }

    // ---------- outputs (float32) ----------
    if (tid == 0) s_mcnt = 0;
    __syncthreads();
    float* out_sel = out;
    float* out_gt  = out + Bn * Qn;
    float* out_mq  = out + 2 * Bn * Qn;
    for (int q = tid; q < Qn; q += 1024) {
        int r = s_rcnt[q];
        out_sel[(size_t)b * Qn + q] = (r > 0) ? 1.0f : 0.0f;
        if (r > 0) { int k = atomicAdd(&s_mcnt, 1); s_mlist[k] = (unsigned short)q; }
        int first = 0;
#pragma unroll
        for (int w = 7; w >= 0; w--) {
            unsigned bits = mb[q * 8 + w];
            if (bits) first = w * 32 + __ffs(bits) - 1;
        }
        out_gt[(size_t)b * Qn + q] = (float)first;
    }
    __syncthreads();
    int nm = s_mcnt;
    for (int g = wid; g < Gn; g += 32) {
        const float* col = Cb + (size_t)g * Qn;
        int wsel = g >> 5; unsigned bsel = 1u << (g & 31);
        float bv = INFINITY; int bi = 0;
        for (int j = lane; j < nm; j += 32) {
            int q = s_mlist[j];
            if (mb[q * 8 + wsel] & bsel) {
                float v = col[q];
                int p = s_pen[q];
                for (int k = 0; k < p; k++) v += 100000.0f;  // sequential fp accumulation
                if (v < bv || (v == bv && q < bi)) { bv = v; bi = q; }
            }
        }
        warpMinPair(bv, bi);
        if (lane == 0) out_mq[(size_t)b * Gn + g] = (float)bi;
    }
}

// ---------------- launch ----------------
extern "C" void kernel_launch(void* const* d_in, const int* in_sizes, int n_in,
                              void* d_out, int out_size) {
    const float* pred_logits = (const float*)d_in[0];
    const float* pred_boxes  = (const float*)d_in[1];
    const float* pred_poses  = (const float*)d_in[2];
    const int*   labels      = (const int*)  d_in[3];
    const float* gt_boxes    = (const float*)d_in[4];
    const float* gt_trans    = (const float*)d_in[5];
    const float* gt_rot      = (const float*)d_in[6];
    const float* isz         = (const float*)d_in[7];
    const float* iszt        = (const float*)d_in[8];
    float* out = (float*)d_out;

    tab_kernel<<<(Bn * Qn + 255) / 256, 256>>>(pred_logits);
    fg_kernel<<<dim3(Qn / 256, Bn), 256>>>(pred_boxes, gt_boxes);
    cost_kernel<<<dim3(Qn / 256, Gn, Bn), 256>>>(pred_boxes, pred_poses, labels,
                                                 gt_boxes, gt_trans, gt_rot, isz, iszt);
    dk_kernel<<<dim3(Gn / 4, Bn), 128>>>(pred_boxes, gt_boxes);
    short_kernel<<<(Bn * Gn) / 4, 128>>>();
    match_kernel<<<Bn, 1024>>>(out);
}

// round 9
// speedup vs baseline: 1.8066x; 1.0238x over previous
#include <cuda_runtime.h>
#include <cuda_bf16.h>
#include <math.h>
#include <stdint.h>

#define Bn 16
#define Qn 4096
#define Gn 256
#define Cn 80
#define Ks 16   // shortlist size per column

// ---------------- device scratch ----------------
__device__ float g_tab[(size_t)Bn * Cn * Qn];          // [b][c][q]
__device__ unsigned char g_fgm[(size_t)Bn * Qn];
__device__ float g_cost[(size_t)Bn * Gn * Qn];         // [b][g][q]
__device__ int g_dk[(size_t)Bn * Gn];
__device__ int g_sidx[(size_t)Bn * Gn * Ks];           // lexicographic (cost,q) top-16 per column
__device__ unsigned g_mb[(size_t)Bn * Qn * 8];         // row bitmasks (256 bits)

// ---------------- helpers ----------------
__device__ __forceinline__ void warpMinPair(float &v, int &i) {
#pragma unroll
    for (int off = 16; off; off >>= 1) {
        float ov = __shfl_xor_sync(0xffffffffu, v, off);
        int   oi = __shfl_xor_sync(0xffffffffu, i, off);
        if (ov < v || (ov == v && oi < i)) { v = ov; i = oi; }
    }
}

// FMA-pipe natural log (Cephes-style, ~1ulp), no MUFU usage.
__device__ __forceinline__ float fma_log(float v) {
    unsigned ix = __float_as_uint(v);
    unsigned ex = (ix - 0x3f3504f3u) & 0xff800000u;  // mantissa in [sqrt(.5), sqrt(2))
    float m = __uint_as_float(ix - ex);
    float k = (float)((int)ex >> 23);
    float f = m - 1.0f;
    float z = f * f;
    float p = 7.0376836292e-2f;
    p = fmaf(p, f, -1.1514610310e-1f);
    p = fmaf(p, f,  1.1676998740e-1f);
    p = fmaf(p, f, -1.2420140846e-1f);
    p = fmaf(p, f,  1.4249322787e-1f);
    p = fmaf(p, f, -1.6668057665e-1f);
    p = fmaf(p, f,  2.0000714765e-1f);
    p = fmaf(p, f, -2.4999993993e-1f);
    p = fmaf(p, f,  3.3333331174e-1f);
    float y = p * f * z;
    y = fmaf(-2.12194440e-4f, k, y);
    y = fmaf(-0.5f, z, y);
    float r = f + y;
    return fmaf(0.693359375f, k, r);
}

// ---------------- K0: class cost table (2 MUFU/elt) ----------------
__global__ void tab_kernel(const float* __restrict__ logits) {
    int idx = blockIdx.x * 256 + threadIdx.x;   // over B*Q
    if (idx >= Bn * Qn) return;
    const float4* row = reinterpret_cast<const float4*>(logits + (size_t)idx * Cn);
    float* dst = g_tab + ((size_t)(idx / Qn) * Cn) * Qn + (idx % Qn);
#pragma unroll 4
    for (int c4 = 0; c4 < Cn / 4; c4++) {
        float4 xv = row[c4];
        float xs[4] = {xv.x, xv.y, xv.z, xv.w};
#pragma unroll
        for (int j = 0; j < 4; j++) {
            float x = xs[j];
            float e = __expf(-x);
            float pr = __fdividef(1.0f, 1.0f + e);
            float om = 1.0f - pr;
            float neg = 0.75f * (pr * pr) * (-fma_log(om + 1e-8f));
            float pos = 0.25f * (om * om) * (-fma_log(pr + 1e-8f));
            dst[(size_t)(c4 * 4 + j) * Qn] = pos - neg;
        }
    }
}

// ---------------- K1: fg mask ----------------
__global__ void fg_kernel(const float* __restrict__ pred_boxes,
                          const float* __restrict__ gt_boxes) {
    __shared__ float s[Gn][8];
    int b = blockIdx.y;
    int q = blockIdx.x * 256 + threadIdx.x;
    int tid = threadIdx.x;
    {
        const float* gb = gt_boxes + ((size_t)b * Gn + tid) * 4;
        float gx0 = gb[0], gy0 = gb[1], gx1 = gb[2], gy1 = gb[3];
        float cx = (gx0 + gx1) * 0.5f, cy = (gy0 + gy1) * 0.5f;
        float gw = gx1 - gx0, gh = gy1 - gy0;
        float x0 = cx - gw * 0.5f, y0 = cy - gh * 0.5f;
        float x1 = cx + gw * 0.5f, y1 = cy + gh * 0.5f;
        float w = x1 - x0, h = y1 - y0;
        s[tid][0] = x0; s[tid][1] = y0; s[tid][2] = x1; s[tid][3] = y1;
        s[tid][4] = cx - 2.5f * w; s[tid][5] = cx + 2.5f * w;
        s[tid][6] = cy - 2.5f * h; s[tid][7] = cy + 2.5f * h;
    }
    __syncthreads();
    float4 p = reinterpret_cast<const float4*>(pred_boxes)[(size_t)b * Qn + q];
    float ax = (p.x + p.z) * 0.5f, ay = (p.y + p.w) * 0.5f;
    unsigned char fg = 0;
    for (int g = 0; g < Gn; g++) {
        bool ib = (ax > s[g][0]) && (ax < s[g][2]) && (ay > s[g][1]) && (ay < s[g][3]);
        bool ic = (ax > s[g][4]) && (ax < s[g][5]) && (ay > s[g][6]) && (ay < s[g][7]);
        if (ib || ic) { fg = 1; break; }
    }
    g_fgm[(size_t)b * Qn + q] = fg;
}

// ---------------- K2: full pairwise cost ----------------
__global__ void cost_kernel(const float* __restrict__ pred_boxes,
                            const float* __restrict__ pred_poses,
                            const int*   __restrict__ labels,
                            const float* __restrict__ gt_boxes,
                            const float* __restrict__ gt_t,
                            const float* __restrict__ gt_r,
                            const float* __restrict__ isz,
                            const float* __restrict__ iszt) {
    int q = blockIdx.x * 256 + threadIdx.x;
    int g = blockIdx.y;
    int b = blockIdx.z;

    const float* gb = gt_boxes + ((size_t)b * Gn + g) * 4;
    float gx0 = gb[0], gy0 = gb[1], gx1 = gb[2], gy1 = gb[3];
    const float* t3 = gt_t + ((size_t)b * Gn + g) * 3;
    const float* r3 = gt_r + ((size_t)b * Gn + g) * 3;
    int lab = labels[b * Gn + g];
    const float* is  = isz + (size_t)b * 4;
    const float* ist = iszt + ((size_t)b * Gn + g) * 4;

    float4 p = reinterpret_cast<const float4*>(pred_boxes)[(size_t)b * Qn + q];
    const float* ps = pred_poses + ((size_t)b * Qn + q) * 6;

    float area1 = (p.z - p.x) * (p.w - p.y);
    float area2 = (gx1 - gx0) * (gy1 - gy0);
    float lx = fmaxf(p.x, gx0), ly = fmaxf(p.y, gy0);
    float rx = fminf(p.z, gx1), ry = fminf(p.w, gy1);
    float wx = fmaxf(rx - lx, 0.0f), wy = fmaxf(ry - ly, 0.0f);
    float inter = wx * wy;
    float uni = area1 + area2 - inter;
    float iou = inter / uni;
    float Lx = fminf(p.x, gx0), Ly = fminf(p.y, gy0);
    float Rx = fmaxf(p.z, gx1), Ry = fmaxf(p.w, gy1);
    float ew = fmaxf(Rx - Lx, 0.0f), eh = fmaxf(Ry - Ly, 0.0f);
    float areaE = ew * eh;
    float giou = iou - (areaE - uni) / areaE;

    float cb = fabsf(p.x / is[0] - gx0 / ist[0])
             + fabsf(p.y / is[1] - gy0 / ist[1])
             + fabsf(p.z / is[2] - gx1 / ist[2])
             + fabsf(p.w / is[3] - gy1 / ist[3]);

    float cc = g_tab[((size_t)b * Cn + lab) * Qn + q];

    float ct = fabsf(ps[0] - t3[0]) + fabsf(ps[1] - t3[1]) + fabsf(ps[2] - t3[2]);
    float cr = fabsf(ps[3] - r3[0]) + fabsf(ps[4] - r3[1]) + fabsf(ps[5] - r3[2]);

    float ax = (p.x + p.z) * 0.5f, ay = (p.y + p.w) * 0.5f;
    float gcx = (gx0 + gx1) * 0.5f, gcy = (gy0 + gy1) * 0.5f;
    float gw = gx1 - gx0, gh = gy1 - gy0;
    float x0 = gcx - gw * 0.5f, y0 = gcy - gh * 0.5f;
    float x1 = gcx + gw * 0.5f, y1 = gcy + gh * 0.5f;
    bool in_box = (ax > x0) && (ax < x1) && (ay > y0) && (ay < y1);
    float w = x1 - x0, h = y1 - y0;
    bool in_ctr = (ax > gcx - 2.5f * w) && (ax < gcx + 2.5f * w) &&
                  (ay > gcy - 2.5f * h) && (ay < gcy + 2.5f * h);
    bool both = in_box && in_ctr;

    float cost = 5.0f * cb + 2.0f * cc + 2.0f * (-giou)
               + 100.0f * (both ? 0.0f : 1.0f) + 1.0f * ct + 1.0f * cr;
    cost += g_fgm[(size_t)b * Qn + q] ? 0.0f : 10000.0f;

    g_cost[((size_t)b * Gn + g) * Qn + q] = cost;
}

// ---------------- K3: per-column dk (iou top-5 sum), 2-way ILP ----------------
__device__ __forceinline__ float iou_one(float4 p, float gx0, float gy0,
                                         float gx1, float gy1, float area2) {
    float a1 = (p.z - p.x) * (p.w - p.y);
    float lx = fmaxf(p.x, gx0), ly = fmaxf(p.y, gy0);
    float rx = fminf(p.z, gx1), ry = fminf(p.w, gy1);
    float wx = fmaxf(rx - lx, 0.0f), wy = fmaxf(ry - ly, 0.0f);
    float inter = wx * wy;
    return inter / (a1 + area2 - inter);
}

__global__ void dk_kernel(const float* __restrict__ pred_boxes,
                          const float* __restrict__ gt_boxes) {
    int warp = threadIdx.x >> 5, lane = threadIdx.x & 31;
    int g = blockIdx.x * 8 + warp;
    int b = blockIdx.y;
    const float4* pb = reinterpret_cast<const float4*>(pred_boxes) + (size_t)b * Qn;
    const float* gb = gt_boxes + ((size_t)b * Gn + g) * 4;
    float gx0 = gb[0], gy0 = gb[1], gx1 = gb[2], gy1 = gb[3];
    float area2 = (gx1 - gx0) * (gy1 - gy0);

    float iv[5];
#pragma unroll
    for (int k = 0; k < 5; k++) iv[k] = -INFINITY;

#pragma unroll 2
    for (int i = 0; i < Qn / 64; i++) {
        float4 pa = pb[lane + 64 * i];
        float4 pc = pb[lane + 64 * i + 32];
        float ia = iou_one(pa, gx0, gy0, gx1, gy1, area2);
        float ic = iou_one(pc, gx0, gy0, gx1, gy1, area2);
        if (ia > iv[4]) {
            iv[4] = ia;
#pragma unroll
            for (int k = 4; k > 0; k--) {
                float lo = fminf(iv[k], iv[k - 1]);
                float hi = fmaxf(iv[k], iv[k - 1]);
                iv[k] = lo; iv[k - 1] = hi;
            }
        }
        if (ic > iv[4]) {
            iv[4] = ic;
#pragma unroll
            for (int k = 4; k > 0; k--) {
                float lo = fminf(iv[k], iv[k - 1]);
                float hi = fmaxf(iv[k], iv[k - 1]);
                iv[k] = lo; iv[k - 1] = hi;
            }
        }
    }

    // iou top-5 sum across warp (descending extraction)
    int p5 = 0; float sum = 0.0f;
    for (int r = 0; r < 5; r++) {
        float cand = (p5 < 5) ? iv[p5] : -INFINITY;
        float m = cand;
#pragma unroll
        for (int off = 16; off; off >>= 1) m = fmaxf(m, __shfl_xor_sync(0xffffffffu, m, off));
        sum += m;
        unsigned ball = __ballot_sync(0xffffffffu, cand == m);
        if (lane == (__ffs(ball) - 1)) p5++;
    }
    int dk = (int)sum;
    if (dk < 1) dk = 1;
    if (dk > 5) dk = 5;
    if (lane == 0) g_dk[(size_t)b * Gn + g] = dk;
}

// ---------------- K4: per-column lexicographic cost top-16 (u64 keys) ----------------
__device__ __forceinline__ unsigned long long costKey(float v, int q) {
    unsigned bits = __float_as_uint(v);
    unsigned mk = (bits & 0x80000000u) ? ~bits : (bits ^ 0x80000000u);
    return ((unsigned long long)mk << 32) | (unsigned)q;
}

__global__ void short_kernel() {
    int warp = threadIdx.x >> 5, lane = threadIdx.x & 31;
    int col = blockIdx.x * 4 + warp;        // over Bn*Gn columns
    const float4* c4 = reinterpret_cast<const float4*>(g_cost + (size_t)col * Qn);

    unsigned long long t[Ks];
#pragma unroll
    for (int k = 0; k < Ks; k++) t[k] = ~0ull;

    for (int i = lane; i < Qn / 4; i += 32) {
        float4 v = c4[i];
        int q0 = i * 4;
#pragma unroll
        for (int j = 0; j < 4; j++) {
            float vv = (j == 0) ? v.x : (j == 1) ? v.y : (j == 2) ? v.z : v.w;
            unsigned long long key = costKey(vv, q0 + j);
            if (key < t[Ks - 1]) {
                t[Ks - 1] = key;
#pragma unroll
                for (int k = Ks - 1; k > 0; k--) {
                    unsigned long long a = t[k - 1], bb = t[k];
                    t[k - 1] = (a < bb) ? a : bb;
                    t[k]     = (a < bb) ? bb : a;
                }
            }
        }
    }

    // warp merge: 16 rounds of u64 min extraction (keys are unique: q embedded)
    int p = 0;
    int* dst = g_sidx + (size_t)col * Ks;
    for (int r = 0; r < Ks; r++) {
        unsigned long long cand = (p < Ks) ? t[p] : ~0ull;
        unsigned long long m = cand;
#pragma unroll
        for (int off = 16; off; off >>= 1) {
            unsigned long long o = __shfl_xor_sync(0xffffffffu, m, off);
            if (o < m) m = o;
        }
        if (cand == m) {  // exactly one lane
            p++;
            dst[r] = (int)(m & 0xffffffffu);
        }
    }
}

// ---------------- K5: matching ----------------
__device__ __forceinline__ void reset_row_sh(unsigned* mb, int* s_rcnt, int* s_col,
                                             int q, int r) {
#pragma unroll
    for (int w = 0; w < 8; w++) {
        unsigned bits = mb[q * 8 + w];
        unsigned keep = ((r >> 5) == w) ? (1u << (r & 31)) : 0u;
        unsigned clr = bits & ~keep;
        while (clr) {
            int gp = __ffs(clr) - 1; clr &= clr - 1;
            atomicSub(&s_col[w * 32 + gp], 1);
        }
        if (keep && !(bits & keep)) atomicAdd(&s_col[r], 1);
        mb[q * 8 + w] = keep;
    }
    s_rcnt[q] = 1;
}

__global__ void __launch_bounds__(1024, 1) match_kernel(float* __restrict__ out) {
    int b = blockIdx.x, tid = threadIdx.x;
    int wid = tid >> 5, lane = tid & 31;
    const float* Cb = g_cost + (size_t)b * Gn * Qn;
    unsigned* mb = g_mb + (size_t)b * Qn * 8;
    const int* sidx = g_sidx + (size_t)b * Gn * Ks;

    __shared__ int s_rcnt[Qn];
    __shared__ unsigned short s_pen[Qn];
    __shared__ unsigned char s_rg8[Qn];
    __shared__ unsigned s_mat[Qn / 32];
    __shared__ unsigned s_stale[Qn / 32];
    __shared__ int s_col[Gn];
    __shared__ unsigned short s_un[Gn], s_fb[Gn];
    __shared__ unsigned short s_slist[1024];
    __shared__ unsigned short s_mlist[Qn];
    __shared__ int s_ucnt, s_fbcnt, s_conf, s_scnt, s_mcnt;

    for (int i = tid; i < Qn * 8; i += 1024) mb[i] = 0u;
    for (int i = tid; i < Qn; i += 1024) { s_rcnt[i] = 0; s_pen[i] = 0; }
    for (int i = tid; i < Qn / 32; i += 1024) s_stale[i] = 0u;
    if (tid < Gn) s_col[tid] = g_dk[b * Gn + tid];
    if (tid == 0) s_scnt = 0;
    __syncthreads();

    // initial matches: first dk entries of the shortlist
    if (tid < Gn) {
        int dk = s_col[tid];
        for (int j = 0; j < dk; j++) {
            int q = sidx[tid * Ks + j];
            atomicOr(&mb[q * 8 + (tid >> 5)], 1u << (tid & 31));
            atomicAdd(&s_rcnt[q], 1);
        }
    }
    __syncthreads();
    for (int q = tid; q < Qn; q += 1024)
        if (s_rcnt[q] > 1) {
            atomicOr(&s_stale[q >> 5], 1u << (q & 31));
            int k = atomicAdd(&s_scnt, 1);
            if (k < 1024) s_slist[k] = (unsigned short)q;
        }
    __syncthreads();
    // lazy rg for stale rows (raw-cost argmin over g, lowest-g tie)
    int ns = s_scnt; if (ns > 1024) ns = 1024;
    for (int s = wid; s < ns; s += 32) {
        int q = s_slist[s];
        float bv = INFINITY; int bg = 0;
        for (int g = lane; g < Gn; g += 32) {
            float v = Cb[(size_t)g * Qn + q];
            if (v < bv) { bv = v; bg = g; }
        }
        warpMinPair(bv, bg);
        if (lane == 0) s_rg8[q] = (unsigned char)bg;
    }
    __syncthreads();
    // pre-loop stale reset
    for (int q = tid; q < Qn; q += 1024)
        if ((s_stale[q >> 5] >> (q & 31)) & 1)
            reset_row_sh(mb, s_rcnt, s_col, q, s_rg8[q]);
    __syncthreads();

    for (int it = 0; it < Gn; it++) {
        if (tid == 0) { s_ucnt = 0; s_fbcnt = 0; s_conf = 0; }
        __syncthreads();
        if (tid < Gn && s_col[tid] == 0) {
            int k = atomicAdd(&s_ucnt, 1); s_un[k] = (unsigned short)tid;
        }
        __syncthreads();
        int nu = s_ucnt;
        if (nu == 0) break;
        // penalties + matched snapshot (iteration-start state)
        for (int q = tid; q < Qn; q += 1024) if (s_rcnt[q] > 0) s_pen[q]++;
        if (tid < Qn / 32) {
            unsigned wb = 0;
#pragma unroll 8
            for (int j = 0; j < 32; j++) if (s_rcnt[tid * 32 + j] > 0) wb |= 1u << j;
            s_mat[tid] = wb;
        }
        __syncthreads();
        // assignments via shortlist walk
        if (tid < nu) {
            int g = s_un[tid];
            int chosen = -1;
            for (int j = 0; j < Ks; j++) {
                int q = sidx[g * Ks + j];
                if (!((s_mat[q >> 5] >> (q & 31)) & 1)) { chosen = q; break; }
            }
            if (chosen >= 0) {
                atomicOr(&mb[chosen * 8 + (g >> 5)], 1u << (g & 31));
                atomicAdd(&s_rcnt[chosen], 1);
                s_col[g] = 1;
            } else {
                int k = atomicAdd(&s_fbcnt, 1); s_fb[k] = (unsigned short)g;
            }
        }
        __syncthreads();
        // exact fallback (shortlist exhausted)
        int nfb = s_fbcnt;
        for (int u = wid; u < nfb; u += 32) {
            int g = s_fb[u];
            const float* col = Cb + (size_t)g * Qn;
            float bv = INFINITY; int bi = 0;
            for (int q = lane; q < Qn; q += 32) {
                if (!((s_mat[q >> 5] >> (q & 31)) & 1)) {
                    float v = col[q];
                    if (v < bv) { bv = v; bi = q; }
                }
            }
            warpMinPair(bv, bi);
            if (bv == INFINITY) {   // degenerate: every row matched
                bv = INFINITY; bi = 0;
                for (int q = lane; q < Qn; q += 32) {
                    float v = col[q] + 100000.0f * (float)s_pen[q];
                    if (v < bv) { bv = v; bi = q; }
                }
                warpMinPair(bv, bi);
            }
            if (lane == 0) {
                atomicOr(&mb[bi * 8 + (g >> 5)], 1u << (g & 31));
                atomicAdd(&s_rcnt[bi], 1);
                s_col[g] = 1;
            }
        }
        __syncthreads();
        for (int q = tid; q < Qn; q += 1024)
            if (s_rcnt[q] > 1) { s_conf = 1; break; }
        __syncthreads();
        if (s_conf) {
            for (int q = tid; q < Qn; q += 1024)
                if ((s_stale[q >> 5] >> (q & 31)) & 1)
                    reset_row_sh(mb, s_rcnt, s_col, q, s_rg8[q]);
            __syncthreads();
        }
    }

    // ---------- outputs (float32) ----------
    if (tid == 0) s_mcnt = 0;
    __syncthreads();
    float* out_sel = out;
    float* out_gt  = out + Bn * Qn;
    float* out_mq  = out + 2 * Bn * Qn;
    for (int q = tid; q < Qn; q += 1024) {
        int r = s_rcnt[q];
        out_sel[(size_t)b * Qn + q] = (r > 0) ? 1.0f : 0.0f;
        if (r > 0) { int k = atomicAdd(&s_mcnt, 1); s_mlist[k] = (unsigned short)q; }
        int first = 0;
#pragma unroll
        for (int w = 7; w >= 0; w--) {
            unsigned bits = mb[q * 8 + w];
            if (bits) first = w * 32 + __ffs(bits) - 1;
        }
        out_gt[(size_t)b * Qn + q] = (float)first;
    }
    __syncthreads();
    int nm = s_mcnt;
    for (int g = wid; g < Gn; g += 32) {
        const float* col = Cb + (size_t)g * Qn;
        int wsel = g >> 5; unsigned bsel = 1u << (g & 31);
        float bv = INFINITY; int bi = 0;
        for (int j = lane; j < nm; j += 32) {
            int q = s_mlist[j];
            if (mb[q * 8 + wsel] & bsel) {
                float v = col[q];
                int p = s_pen[q];
                for (int k = 0; k < p; k++) v += 100000.0f;  // sequential fp accumulation
                if (v < bv || (v == bv && q < bi)) { bv = v; bi = q; }
            }
        }
        warpMinPair(bv, bi);
        if (lane == 0) out_mq[(size_t)b * Gn + g] = (float)bi;
    }
}

// ---------------- launch ----------------
extern "C" void kernel_launch(void* const* d_in, const int* in_sizes, int n_in,
                              void* d_out, int out_size) {
    const float* pred_logits = (const float*)d_in[0];
    const float* pred_boxes  = (const float*)d_in[1];
    const float* pred_poses  = (const float*)d_in[2];
    const int*   labels      = (const int*)  d_in[3];
    const float* gt_boxes    = (const float*)d_in[4];
    const float* gt_trans    = (const float*)d_in[5];
    const float* gt_rot      = (const float*)d_in[6];
    const float* isz         = (const float*)d_in[7];
    const float* iszt        = (const float*)d_in[8];
    float* out = (float*)d_out;

    tab_kernel<<<(Bn * Qn + 255) / 256, 256>>>(pred_logits);
    fg_kernel<<<dim3(Qn / 256, Bn), 256>>>(pred_boxes, gt_boxes);
    cost_kernel<<<dim3(Qn / 256, Gn, Bn), 256>>>(pred_boxes, pred_poses, labels,
                                                 gt_boxes, gt_trans, gt_rot, isz, iszt);
    dk_kernel<<<dim3(Gn / 8, Bn), 256>>>(pred_boxes, gt_boxes);
    short_kernel<<<(Bn * Gn) / 4, 128>>>();
    match_kernel<<<Bn, 1024>>>(out);
}

// round 10
// speedup vs baseline: 1.9784x; 1.0951x over previous
#include <cuda_runtime.h>
#include <cuda_bf16.h>
#include <math.h>
#include <stdint.h>

#define Bn 16
#define Qn 4096
#define Gn 256
#define Cn 80
#define Ks 16   // shortlist size per column

// ---------------- device scratch ----------------
__device__ float g_tab[(size_t)Bn * Cn * Qn];          // [b][c][q]
__device__ unsigned char g_fgm[(size_t)Bn * Qn];
__device__ float g_cost[(size_t)Bn * Gn * Qn];         // [b][g][q]
__device__ int g_dk[(size_t)Bn * Gn];
__device__ int g_sidx[(size_t)Bn * Gn * Ks];           // lexicographic (cost,q) top-16 per column

// ---------------- helpers ----------------
__device__ __forceinline__ void warpMinPair(float &v, int &i) {
#pragma unroll
    for (int off = 16; off; off >>= 1) {
        float ov = __shfl_xor_sync(0xffffffffu, v, off);
        int   oi = __shfl_xor_sync(0xffffffffu, i, off);
        if (ov < v || (ov == v && oi < i)) { v = ov; i = oi; }
    }
}

// FMA-pipe natural log (Cephes-style, ~1ulp), no MUFU usage.
__device__ __forceinline__ float fma_log(float v) {
    unsigned ix = __float_as_uint(v);
    unsigned ex = (ix - 0x3f3504f3u) & 0xff800000u;  // mantissa in [sqrt(.5), sqrt(2))
    float m = __uint_as_float(ix - ex);
    float k = (float)((int)ex >> 23);
    float f = m - 1.0f;
    float z = f * f;
    float p = 7.0376836292e-2f;
    p = fmaf(p, f, -1.1514610310e-1f);
    p = fmaf(p, f,  1.1676998740e-1f);
    p = fmaf(p, f, -1.2420140846e-1f);
    p = fmaf(p, f,  1.4249322787e-1f);
    p = fmaf(p, f, -1.6668057665e-1f);
    p = fmaf(p, f,  2.0000714765e-1f);
    p = fmaf(p, f, -2.4999993993e-1f);
    p = fmaf(p, f,  3.3333331174e-1f);
    float y = p * f * z;
    y = fmaf(-2.12194440e-4f, k, y);
    y = fmaf(-0.5f, z, y);
    float r = f + y;
    return fmaf(0.693359375f, k, r);
}

// ---------------- K0: class cost table ----------------
__global__ void tab_kernel(const float* __restrict__ logits) {
    int idx = blockIdx.x * 256 + threadIdx.x;   // over B*Q
    if (idx >= Bn * Qn) return;
    const float4* row = reinterpret_cast<const float4*>(logits + (size_t)idx * Cn);
    float* dst = g_tab + ((size_t)(idx / Qn) * Cn) * Qn + (idx % Qn);
#pragma unroll 4
    for (int c4 = 0; c4 < Cn / 4; c4++) {
        float4 xv = row[c4];
        float xs[4] = {xv.x, xv.y, xv.z, xv.w};
#pragma unroll
        for (int j = 0; j < 4; j++) {
            float x = xs[j];
            float e = __expf(-x);
            float pr = __fdividef(1.0f, 1.0f + e);
            float om = 1.0f - pr;
            float neg = 0.75f * (pr * pr) * (-fma_log(om + 1e-8f));
            float pos = 0.25f * (om * om) * (-fma_log(pr + 1e-8f));
            dst[(size_t)(c4 * 4 + j) * Qn] = pos - neg;
        }
    }
}

// ---------------- K1: fg mask ----------------
__global__ void fg_kernel(const float* __restrict__ pred_boxes,
                          const float* __restrict__ gt_boxes) {
    __shared__ float s[Gn][8];
    int b = blockIdx.y;
    int q = blockIdx.x * 256 + threadIdx.x;
    int tid = threadIdx.x;
    {
        const float* gb = gt_boxes + ((size_t)b * Gn + tid) * 4;
        float gx0 = gb[0], gy0 = gb[1], gx1 = gb[2], gy1 = gb[3];
        float cx = (gx0 + gx1) * 0.5f, cy = (gy0 + gy1) * 0.5f;
        float gw = gx1 - gx0, gh = gy1 - gy0;
        float x0 = cx - gw * 0.5f, y0 = cy - gh * 0.5f;
        float x1 = cx + gw * 0.5f, y1 = cy + gh * 0.5f;
        float w = x1 - x0, h = y1 - y0;
        s[tid][0] = x0; s[tid][1] = y0; s[tid][2] = x1; s[tid][3] = y1;
        s[tid][4] = cx - 2.5f * w; s[tid][5] = cx + 2.5f * w;
        s[tid][6] = cy - 2.5f * h; s[tid][7] = cy + 2.5f * h;
    }
    __syncthreads();
    float4 p = reinterpret_cast<const float4*>(pred_boxes)[(size_t)b * Qn + q];
    float ax = (p.x + p.z) * 0.5f, ay = (p.y + p.w) * 0.5f;
    unsigned char fg = 0;
    for (int g = 0; g < Gn; g++) {
        bool ib = (ax > s[g][0]) && (ax < s[g][2]) && (ay > s[g][1]) && (ay < s[g][3]);
        bool ic = (ax > s[g][4]) && (ax < s[g][5]) && (ay > s[g][6]) && (ay < s[g][7]);
        if (ib || ic) { fg = 1; break; }
    }
    g_fgm[(size_t)b * Qn + q] = fg;
}

// ---------------- K2: full pairwise cost ----------------
__global__ void cost_kernel(const float* __restrict__ pred_boxes,
                            const float* __restrict__ pred_poses,
                            const int*   __restrict__ labels,
                            const float* __restrict__ gt_boxes,
                            const float* __restrict__ gt_t,
                            const float* __restrict__ gt_r,
                            const float* __restrict__ isz,
                            const float* __restrict__ iszt) {
    int q = blockIdx.x * 256 + threadIdx.x;
    int g = blockIdx.y;
    int b = blockIdx.z;

    const float* gb = gt_boxes + ((size_t)b * Gn + g) * 4;
    float gx0 = gb[0], gy0 = gb[1], gx1 = gb[2], gy1 = gb[3];
    const float* t3 = gt_t + ((size_t)b * Gn + g) * 3;
    const float* r3 = gt_r + ((size_t)b * Gn + g) * 3;
    int lab = labels[b * Gn + g];
    const float* is  = isz + (size_t)b * 4;
    const float* ist = iszt + ((size_t)b * Gn + g) * 4;

    float4 p = reinterpret_cast<const float4*>(pred_boxes)[(size_t)b * Qn + q];
    const float* ps = pred_poses + ((size_t)b * Qn + q) * 6;

    float area1 = (p.z - p.x) * (p.w - p.y);
    float area2 = (gx1 - gx0) * (gy1 - gy0);
    float lx = fmaxf(p.x, gx0), ly = fmaxf(p.y, gy0);
    float rx = fminf(p.z, gx1), ry = fminf(p.w, gy1);
    float wx = fmaxf(rx - lx, 0.0f), wy = fmaxf(ry - ly, 0.0f);
    float inter = wx * wy;
    float uni = area1 + area2 - inter;
    float iou = inter / uni;
    float Lx = fminf(p.x, gx0), Ly = fminf(p.y, gy0);
    float Rx = fmaxf(p.z, gx1), Ry = fmaxf(p.w, gy1);
    float ew = fmaxf(Rx - Lx, 0.0f), eh = fmaxf(Ry - Ly, 0.0f);
    float areaE = ew * eh;
    float giou = iou - (areaE - uni) / areaE;

    float cb = fabsf(p.x / is[0] - gx0 / ist[0])
             + fabsf(p.y / is[1] - gy0 / ist[1])
             + fabsf(p.z / is[2] - gx1 / ist[2])
             + fabsf(p.w / is[3] - gy1 / ist[3]);

    float cc = g_tab[((size_t)b * Cn + lab) * Qn + q];

    float ct = fabsf(ps[0] - t3[0]) + fabsf(ps[1] - t3[1]) + fabsf(ps[2] - t3[2]);
    float cr = fabsf(ps[3] - r3[0]) + fabsf(ps[4] - r3[1]) + fabsf(ps[5] - r3[2]);

    float ax = (p.x + p.z) * 0.5f, ay = (p.y + p.w) * 0.5f;
    float gcx = (gx0 + gx1) * 0.5f, gcy = (gy0 + gy1) * 0.5f;
    float gw = gx1 - gx0, gh = gy1 - gy0;
    float x0 = gcx - gw * 0.5f, y0 = gcy - gh * 0.5f;
    float x1 = gcx + gw * 0.5f, y1 = gcy + gh * 0.5f;
    bool in_box = (ax > x0) && (ax < x1) && (ay > y0) && (ay < y1);
    float w = x1 - x0, h = y1 - y0;
    bool in_ctr = (ax > gcx - 2.5f * w) && (ax < gcx + 2.5f * w) &&
                  (ay > gcy - 2.5f * h) && (ay < gcy + 2.5f * h);
    bool both = in_box && in_ctr;

    float cost = 5.0f * cb + 2.0f * cc + 2.0f * (-giou)
               + 100.0f * (both ? 0.0f : 1.0f) + 1.0f * ct + 1.0f * cr;
    cost += g_fgm[(size_t)b * Qn + q] ? 0.0f : 10000.0f;

    g_cost[((size_t)b * Gn + g) * Qn + q] = cost;
}

// ---------------- K3: per-column dk, block-per-column (4 warps) ----------------
__device__ __forceinline__ float iou_one(float4 p, float gx0, float gy0,
                                         float gx1, float gy1, float area2) {
    float a1 = (p.z - p.x) * (p.w - p.y);
    float lx = fmaxf(p.x, gx0), ly = fmaxf(p.y, gy0);
    float rx = fminf(p.z, gx1), ry = fminf(p.w, gy1);
    float wx = fmaxf(rx - lx, 0.0f), wy = fmaxf(ry - ly, 0.0f);
    float inter = wx * wy;
    return inter / (a1 + area2 - inter);
}

__global__ void dk_kernel(const float* __restrict__ pred_boxes,
                          const float* __restrict__ gt_boxes) {
    int g = blockIdx.x, b = blockIdx.y;
    int wrp = threadIdx.x >> 5, lane = threadIdx.x & 31;
    const float4* pb = reinterpret_cast<const float4*>(pred_boxes) + (size_t)b * Qn;
    const float* gb = gt_boxes + ((size_t)b * Gn + g) * 4;
    float gx0 = gb[0], gy0 = gb[1], gx1 = gb[2], gy1 = gb[3];
    float area2 = (gx1 - gx0) * (gy1 - gy0);

    __shared__ float s5[4][5];

    float iv[5];
#pragma unroll
    for (int k = 0; k < 5; k++) iv[k] = -INFINITY;

    int base = wrp * 1024 + lane;
#pragma unroll 2
    for (int i = 0; i < 16; i++) {
        float4 pa = pb[base + i * 64];
        float4 pc = pb[base + i * 64 + 32];
        float ia = iou_one(pa, gx0, gy0, gx1, gy1, area2);
        float ic = iou_one(pc, gx0, gy0, gx1, gy1, area2);
        if (ia > iv[4]) {
            iv[4] = ia;
#pragma unroll
            for (int k = 4; k > 0; k--) {
                float lo = fminf(iv[k], iv[k - 1]);
                float hi = fmaxf(iv[k], iv[k - 1]);
                iv[k] = lo; iv[k - 1] = hi;
            }
        }
        if (ic > iv[4]) {
            iv[4] = ic;
#pragma unroll
            for (int k = 4; k > 0; k--) {
                float lo = fminf(iv[k], iv[k - 1]);
                float hi = fmaxf(iv[k], iv[k - 1]);
                iv[k] = lo; iv[k - 1] = hi;
            }
        }
    }

    // per-warp top-5 extraction (descending) -> shared
    int p5 = 0;
    for (int r = 0; r < 5; r++) {
        float cand = (p5 < 5) ? iv[p5] : -INFINITY;
        float m = cand;
#pragma unroll
        for (int off = 16; off; off >>= 1) m = fmaxf(m, __shfl_xor_sync(0xffffffffu, m, off));
        unsigned ball = __ballot_sync(0xffffffffu, cand == m);
        if (lane == (__ffs(ball) - 1)) p5++;
        if (lane == 0) s5[wrp][r] = m;
    }
    __syncthreads();

    if (wrp == 0) {
        float v = -INFINITY;
        if (lane < 20) v = s5[lane / 5][lane % 5];
        int used = 0; float sum = 0.0f;
        for (int r = 0; r < 5; r++) {
            float cand = (used == 0) ? v : -INFINITY;
            float m = cand;
#pragma unroll
            for (int off = 16; off; off >>= 1) m = fmaxf(m, __shfl_xor_sync(0xffffffffu, m, off));
            sum += m;
            unsigned ball = __ballot_sync(0xffffffffu, cand == m);
            if (lane == (__ffs(ball) - 1)) used = 1;
        }
        int dk = (int)sum;
        if (dk < 1) dk = 1;
        if (dk > 5) dk = 5;
        if (lane == 0) g_dk[(size_t)b * Gn + g] = dk;
    }
}

// ---------------- K4: per-column lexicographic cost top-16 (u64 keys) ----------------
__device__ __forceinline__ unsigned long long costKey(float v, int q) {
    unsigned bits = __float_as_uint(v);
    unsigned mk = (bits & 0x80000000u) ? ~bits : (bits ^ 0x80000000u);
    return ((unsigned long long)mk << 32) | (unsigned)q;
}

__global__ void short_kernel() {
    int warp = threadIdx.x >> 5, lane = threadIdx.x & 31;
    int col = blockIdx.x * 4 + warp;        // over Bn*Gn columns
    const float4* c4 = reinterpret_cast<const float4*>(g_cost + (size_t)col * Qn);

    unsigned long long t[Ks];
#pragma unroll
    for (int k = 0; k < Ks; k++) t[k] = ~0ull;

    for (int i = lane; i < Qn / 4; i += 32) {
        float4 v = c4[i];
        int q0 = i * 4;
#pragma unroll
        for (int j = 0; j < 4; j++) {
            float vv = (j == 0) ? v.x : (j == 1) ? v.y : (j == 2) ? v.z : v.w;
            unsigned long long key = costKey(vv, q0 + j);
            if (key < t[Ks - 1]) {
                t[Ks - 1] = key;
#pragma unroll
                for (int k = Ks - 1; k > 0; k--) {
                    unsigned long long a = t[k - 1], bb = t[k];
                    t[k - 1] = (a < bb) ? a : bb;
                    t[k]     = (a < bb) ? bb : a;
                }
            }
        }
    }

    int p = 0;
    int* dst = g_sidx + (size_t)col * Ks;
    for (int r = 0; r < Ks; r++) {
        unsigned long long cand = (p < Ks) ? t[p] : ~0ull;
        unsigned long long m = cand;
#pragma unroll
        for (int off = 16; off; off >>= 1) {
            unsigned long long o = __shfl_xor_sync(0xffffffffu, m, off);
            if (o < m) m = o;
        }
        if (cand == m) {
            p++;
            dst[r] = (int)(m & 0xffffffffu);
        }
    }
}

// ---------------- K5: matching (all shared, no bitmask) ----------------
__global__ void __launch_bounds__(1024, 1) match_kernel(float* __restrict__ out) {
    int b = blockIdx.x, tid = threadIdx.x;
    int wid = tid >> 5, lane = tid & 31;
    const float* Cb = g_cost + (size_t)b * Gn * Qn;
    const int* sidx = g_sidx + (size_t)b * Gn * Ks;

    __shared__ int s_rcnt[Qn];                 // 16KB
    __shared__ unsigned char s_pen[Qn];        // 4KB
    __shared__ int s_ming[Qn];                 // 16KB  (min matched g)
    __shared__ unsigned char s_rg8[Qn];        // 4KB   (valid only for stale rows)
    __shared__ unsigned s_mat[Qn / 32];        // matched snapshot
    __shared__ unsigned s_stale[Qn / 32];
    __shared__ int s_col[Gn];
    __shared__ unsigned char s_dk[Gn];
    __shared__ short s_asg[Gn];                // assigned row per column, -1 = none
    __shared__ unsigned short s_un[Gn], s_fb[Gn];
    __shared__ unsigned short s_slist[1024];
    __shared__ int s_ucnt, s_fbcnt, s_scnt;

    for (int i = tid; i < Qn; i += 1024) { s_rcnt[i] = 0; s_pen[i] = 0; s_ming[i] = 0x7fffffff; }
    for (int i = tid; i < Qn / 32; i += 1024) s_stale[i] = 0u;
    if (tid < Gn) { s_dk[tid] = (unsigned char)g_dk[b * Gn + tid]; s_col[tid] = 0; s_asg[tid] = -1; }
    if (tid == 0) s_scnt = 0;
    __syncthreads();

    // Phase A: raw initial counts
    if (tid < Gn) {
        int dk = s_dk[tid];
        for (int j = 0; j < dk; j++) atomicAdd(&s_rcnt[sidx[tid * Ks + j]], 1);
    }
    __syncthreads();
    // Phase B: stale rows (raw count > 1)
    for (int q = tid; q < Qn; q += 1024)
        if (s_rcnt[q] > 1) {
            atomicOr(&s_stale[q >> 5], 1u << (q & 31));
            int k = atomicAdd(&s_scnt, 1);
            if (k < 1024) s_slist[k] = (unsigned short)q;
        }
    __syncthreads();
    // Phase C: rg for stale rows (raw-cost argmin over g, lowest-g tie)
    int ns = s_scnt; if (ns > 1024) ns = 1024;
    for (int s = wid; s < ns; s += 32) {
        int q = s_slist[s];
        float bv = INFINITY; int bg = 0;
        for (int g = lane; g < Gn; g += 32) {
            float v = Cb[(size_t)g * Qn + q];
            if (v < bv) { bv = v; bg = g; }
        }
        warpMinPair(bv, bg);
        if (lane == 0) s_rg8[q] = (unsigned char)bg;
    }
    __syncthreads();
    // Phase D: rebuild final initial state (stale rows collapsed to {rg})
    for (int q = tid; q < Qn; q += 1024) s_rcnt[q] = 0;
    __syncthreads();
    if (tid < Gn) {
        int dk = s_dk[tid];
        for (int j = 0; j < dk; j++) {
            int q = sidx[tid * Ks + j];
            if (!((s_stale[q >> 5] >> (q & 31)) & 1)) {
                atomicAdd(&s_rcnt[q], 1);
                atomicAdd(&s_col[tid], 1);
                atomicMin(&s_ming[q], tid);
            }
        }
    }
    for (int s = tid; s < ns; s += 1024) {
        int q = s_slist[s];
        int rg = s_rg8[q];
        s_rcnt[q] = 1;
        s_ming[q] = rg;
        atomicAdd(&s_col[rg], 1);
    }
    __syncthreads();

    // Dynamic-K completion loop (provably converges fast; resets are no-ops)
    for (int it = 0; it < Gn; it++) {
        if (tid == 0) { s_ucnt = 0; s_fbcnt = 0; }
        __syncthreads();
        if (tid < Gn && s_col[tid] == 0) {
            int k = atomicAdd(&s_ucnt, 1); s_un[k] = (unsigned short)tid;
        }
        __syncthreads();
        int nu = s_ucnt;
        if (nu == 0) break;
        // penalties + matched snapshot (iteration-start state)
        for (int q = tid; q < Qn; q += 1024) if (s_rcnt[q] > 0) s_pen[q]++;
        if (tid < Qn / 32) {
            unsigned wb = 0;
#pragma unroll 8
            for (int j = 0; j < 32; j++) if (s_rcnt[tid * 32 + j] > 0) wb |= 1u << j;
            s_mat[tid] = wb;
        }
        __syncthreads();
        // assignments via shortlist walk (argmin over unmatched rows)
        if (tid < nu) {
            int g = s_un[tid];
            int chosen = -1;
            for (int j = 0; j < Ks; j++) {
                int q = sidx[g * Ks + j];
                if (!((s_mat[q >> 5] >> (q & 31)) & 1)) { chosen = q; break; }
            }
            if (chosen >= 0) {
                atomicAdd(&s_rcnt[chosen], 1);
                atomicMin(&s_ming[chosen], g);
                s_col[g] = 1;
                s_asg[g] = (short)chosen;
            } else {
                int k = atomicAdd(&s_fbcnt, 1); s_fb[k] = (unsigned short)g;
            }
        }
        __syncthreads();
        // exact fallback (shortlist exhausted)
        int nfb = s_fbcnt;
        for (int u = wid; u < nfb; u += 32) {
            int g = s_fb[u];
            const float* col = Cb + (size_t)g * Qn;
            float bv = INFINITY; int bi = 0;
            for (int q = lane; q < Qn; q += 32) {
                if (!((s_mat[q >> 5] >> (q & 31)) & 1)) {
                    float v = col[q];
                    if (v < bv) { bv = v; bi = q; }
                }
            }
            warpMinPair(bv, bi);
            if (bv == INFINITY) {   // degenerate: every row matched
                bv = INFINITY; bi = 0;
                for (int q = lane; q < Qn; q += 32) {
                    float v = col[q] + 100000.0f * (float)s_pen[q];
                    if (v < bv) { bv = v; bi = q; }
                }
                warpMinPair(bv, bi);
            }
            if (lane == 0) {
                atomicAdd(&s_rcnt[bi], 1);
                atomicMin(&s_ming[bi], g);
                s_col[g] = 1;
                s_asg[g] = (short)bi;
            }
        }
        __syncthreads();
    }

    // ---------- outputs (float32) ----------
    float* out_sel = out;
    float* out_gt  = out + Bn * Qn;
    float* out_mq  = out + 2 * Bn * Qn;
    for (int q = tid; q < Qn; q += 1024) {
        int r = s_rcnt[q];
        out_sel[(size_t)b * Qn + q] = (r > 0) ? 1.0f : 0.0f;
        out_gt[(size_t)b * Qn + q] = (r > 0) ? (float)s_ming[q] : 0.0f;
    }
    // matched_qidx: enumerate candidates per column
    if (tid < Gn) {
        int g = tid;
        const float* col = Cb + (size_t)g * Qn;
        float bv = INFINITY; int bi = 0;
        // 1) non-stale top-dk rows
        int dk = s_dk[g];
        for (int j = 0; j < dk; j++) {
            int q = sidx[g * Ks + j];
            if (!((s_stale[q >> 5] >> (q & 31)) & 1)) {
                float v = col[q];
                int p = s_pen[q];
                for (int k = 0; k < p; k++) v += 100000.0f;
                if (v < bv || (v == bv && q < bi)) { bv = v; bi = q; }
            }
        }
        // 2) stale rows whose rg == g
        for (int s = 0; s < ns; s++) {
            int q = s_slist[s];
            if (s_rg8[q] == g) {
                float v = col[q];
                int p = s_pen[q];
                for (int k = 0; k < p; k++) v += 100000.0f;
                if (v < bv || (v == bv && q < bi)) { bv = v; bi = q; }
            }
        }
        // 3) assigned row
        int aq = s_asg[g];
        if (aq >= 0) {
            float v = col[aq];
            int p = s_pen[aq];
            for (int k = 0; k < p; k++) v += 100000.0f;
            if (v < bv || (v == bv && aq < bi)) { bv = v; bi = aq; }
        }
        out_mq[(size_t)b * Gn + g] = (float)bi;
    }
}

// ---------------- launch ----------------
extern "C" void kernel_launch(void* const* d_in, const int* in_sizes, int n_in,
                              void* d_out, int out_size) {
    const float* pred_logits = (const float*)d_in[0];
    const float* pred_boxes  = (const float*)d_in[1];
    const float* pred_poses  = (const float*)d_in[2];
    const int*   labels      = (const int*)  d_in[3];
    const float* gt_boxes    = (const float*)d_in[4];
    const float* gt_trans    = (const float*)d_in[5];
    const float* gt_rot      = (const float*)d_in[6];
    const float* isz         = (const float*)d_in[7];
    const float* iszt        = (const float*)d_in[8];
    float* out = (float*)d_out;

    tab_kernel<<<(Bn * Qn + 255) / 256, 256>>>(pred_logits);
    fg_kernel<<<dim3(Qn / 256, Bn), 256>>>(pred_boxes, gt_boxes);
    cost_kernel<<<dim3(Qn / 256, Gn, Bn), 256>>>(pred_boxes, pred_poses, labels,
                                                 gt_boxes, gt_trans, gt_rot, isz, iszt);
    dk_kernel<<<dim3(Gn, Bn), 128>>>(pred_boxes, gt_boxes);
    short_kernel<<<(Bn * Gn) / 4, 128>>>();
    match_kernel<<<Bn, 1024>>>(out);
}

// round 15
// speedup vs baseline: 2.0409x; 1.0316x over previous
#include <cuda_runtime.h>
#include <cuda_bf16.h>
#include <math.h>
#include <stdint.h>

#define Bn 16
#define Qn 4096
#define Gn 256
#define Cn 80
#define Ks 16   // shortlist size per column
#define NBLK 16 // q-blocks per column in cost kernel

// ---------------- device scratch ----------------
__device__ float g_tab[(size_t)Bn * Cn * Qn];          // [b][c][q]
__device__ unsigned char g_fgm[(size_t)Bn * Qn];
__device__ float g_cost[(size_t)Bn * Gn * Qn];         // [b][g][q]
__device__ float g_i5[(size_t)Bn * Gn * NBLK * 5];     // per-block iou top5 partials
__device__ int g_dk[(size_t)Bn * Gn];
__device__ int g_sidx[(size_t)Bn * Gn * Ks];           // lexicographic (cost,q) top-16 per column
__device__ int g_probe;

// ---------------- helpers ----------------
__device__ __forceinline__ void warpMinPair(float &v, int &i) {
#pragma unroll
    for (int off = 16; off; off >>= 1) {
        float ov = __shfl_xor_sync(0xffffffffu, v, off);
        int   oi = __shfl_xor_sync(0xffffffffu, i, off);
        if (ov < v || (ov == v && oi < i)) { v = ov; i = oi; }
    }
}

// FMA-pipe natural log (Cephes-style, ~1ulp), no MUFU usage.
__device__ __forceinline__ float fma_log(float v) {
    unsigned ix = __float_as_uint(v);
    unsigned ex = (ix - 0x3f3504f3u) & 0xff800000u;
    float m = __uint_as_float(ix - ex);
    float k = (float)((int)ex >> 23);
    float f = m - 1.0f;
    float z = f * f;
    float p = 7.0376836292e-2f;
    p = fmaf(p, f, -1.1514610310e-1f);
    p = fmaf(p, f,  1.1676998740e-1f);
    p = fmaf(p, f, -1.2420140846e-1f);
    p = fmaf(p, f,  1.4249322787e-1f);
    p = fmaf(p, f, -1.6668057665e-1f);
    p = fmaf(p, f,  2.0000714765e-1f);
    p = fmaf(p, f, -2.4999993993e-1f);
    p = fmaf(p, f,  3.3333331174e-1f);
    float y = p * f * z;
    y = fmaf(-2.12194440e-4f, k, y);
    y = fmaf(-0.5f, z, y);
    float r = f + y;
    return fmaf(0.693359375f, k, r);
}

// ---------------- probe (slot-alignment no-op) ----------------
__global__ void probe_kernel() { if (threadIdx.x == 1024) g_probe = 1; }

// ---------------- K0: class cost table ----------------
__global__ void tab_kernel(const float* __restrict__ logits) {
    int idx = blockIdx.x * 256 + threadIdx.x;
    if (idx >= Bn * Qn) return;
    const float4* row = reinterpret_cast<const float4*>(logits + (size_t)idx * Cn);
    float* dst = g_tab + ((size_t)(idx / Qn) * Cn) * Qn + (idx % Qn);
#pragma unroll 4
    for (int c4 = 0; c4 < Cn / 4; c4++) {
        float4 xv = row[c4];
        float xs[4] = {xv.x, xv.y, xv.z, xv.w};
#pragma unroll
        for (int j = 0; j < 4; j++) {
            float x = xs[j];
            float e = __expf(-x);
            float pr = __fdividef(1.0f, 1.0f + e);
            float om = 1.0f - pr;
            float neg = 0.75f * (pr * pr) * (-fma_log(om + 1e-8f));
            float pos = 0.25f * (om * om) * (-fma_log(pr + 1e-8f));
            dst[(size_t)(c4 * 4 + j) * Qn] = pos - neg;
        }
    }
}

// ---------------- K1: fg mask ----------------
__global__ void fg_kernel(const float* __restrict__ pred_boxes,
                          const float* __restrict__ gt_boxes) {
    __shared__ float s[Gn][8];
    int b = blockIdx.y;
    int q = blockIdx.x * 256 + threadIdx.x;
    int tid = threadIdx.x;
    {
        const float* gb = gt_boxes + ((size_t)b * Gn + tid) * 4;
        float gx0 = gb[0], gy0 = gb[1], gx1 = gb[2], gy1 = gb[3];
        float cx = (gx0 + gx1) * 0.5f, cy = (gy0 + gy1) * 0.5f;
        float gw = gx1 - gx0, gh = gy1 - gy0;
        float x0 = cx - gw * 0.5f, y0 = cy - gh * 0.5f;
        float x1 = cx + gw * 0.5f, y1 = cy + gh * 0.5f;
        float w = x1 - x0, h = y1 - y0;
        s[tid][0] = x0; s[tid][1] = y0; s[tid][2] = x1; s[tid][3] = y1;
        s[tid][4] = cx - 2.5f * w; s[tid][5] = cx + 2.5f * w;
        s[tid][6] = cy - 2.5f * h; s[tid][7] = cy + 2.5f * h;
    }
    __syncthreads();
    float4 p = reinterpret_cast<const float4*>(pred_boxes)[(size_t)b * Qn + q];
    float ax = (p.x + p.z) * 0.5f, ay = (p.y + p.w) * 0.5f;
    unsigned char fg = 0;
    for (int g = 0; g < Gn; g++) {
        bool ib = (ax > s[g][0]) && (ax < s[g][2]) && (ay > s[g][1]) && (ay < s[g][3]);
        bool ic = (ax > s[g][4]) && (ax < s[g][5]) && (ay > s[g][6]) && (ay < s[g][7]);
        if (ib || ic) { fg = 1; break; }
    }
    g_fgm[(size_t)b * Qn + q] = fg;
}

// ---------------- K2: cost (8 columns per block) + iou top5 partials ----------------
__global__ void cost_kernel(const float* __restrict__ pred_boxes,
                            const float* __restrict__ pred_poses,
                            const int*   __restrict__ labels,
                            const float* __restrict__ gt_boxes,
                            const float* __restrict__ gt_t,
                            const float* __restrict__ gt_r,
                            const float* __restrict__ isz,
                            const float* __restrict__ iszt) {
    int tid = threadIdx.x;
    int q  = blockIdx.x * 256 + tid;
    int g0 = blockIdx.y * 8;
    int b  = blockIdx.z;
    int wrp = tid >> 5, lane = tid & 31;

    __shared__ float s_gt[8][14];   // 0-3 box, 4-6 t, 7-9 r, 10-13 iszt
    __shared__ int   s_lab[8];
    __shared__ float s5w[8][5];

    if (tid < 8) {
        int g = g0 + tid;
        const float* gb = gt_boxes + ((size_t)b * Gn + g) * 4;
        s_gt[tid][0] = gb[0]; s_gt[tid][1] = gb[1]; s_gt[tid][2] = gb[2]; s_gt[tid][3] = gb[3];
        const float* t3 = gt_t + ((size_t)b * Gn + g) * 3;
        s_gt[tid][4] = t3[0]; s_gt[tid][5] = t3[1]; s_gt[tid][6] = t3[2];
        const float* r3 = gt_r + ((size_t)b * Gn + g) * 3;
        s_gt[tid][7] = r3[0]; s_gt[tid][8] = r3[1]; s_gt[tid][9] = r3[2];
        const float* ist = iszt + ((size_t)b * Gn + g) * 4;
        s_gt[tid][10] = ist[0]; s_gt[tid][11] = ist[1]; s_gt[tid][12] = ist[2]; s_gt[tid][13] = ist[3];
        s_lab[tid] = labels[b * Gn + g];
    }
    __syncthreads();

    float4 p = reinterpret_cast<const float4*>(pred_boxes)[(size_t)b * Qn + q];
    const float* psp = pred_poses + ((size_t)b * Qn + q) * 6;
    float ps0 = psp[0], ps1 = psp[1], ps2 = psp[2], ps3 = psp[3], ps4 = psp[4], ps5 = psp[5];
    const float* is = isz + (size_t)b * 4;
    float is0 = is[0], is1 = is[1], is2 = is[2], is3 = is[3];
    float fgpen = g_fgm[(size_t)b * Qn + q] ? 0.0f : 10000.0f;
    float area1 = (p.z - p.x) * (p.w - p.y);
    float ax = (p.x + p.z) * 0.5f, ay = (p.y + p.w) * 0.5f;
    float nx0 = p.x / is0, ny0 = p.y / is1, nx1 = p.z / is2, ny1 = p.w / is3;

    for (int jg = 0; jg < 8; jg++) {
        int g = g0 + jg;
        float gx0 = s_gt[jg][0], gy0 = s_gt[jg][1], gx1 = s_gt[jg][2], gy1 = s_gt[jg][3];

        float area2 = (gx1 - gx0) * (gy1 - gy0);
        float lx = fmaxf(p.x, gx0), ly = fmaxf(p.y, gy0);
        float rx = fminf(p.z, gx1), ry = fminf(p.w, gy1);
        float wx = fmaxf(rx - lx, 0.0f), wy = fmaxf(ry - ly, 0.0f);
        float inter = wx * wy;
        float uni = area1 + area2 - inter;
        float iou = inter / uni;
        float Lx = fminf(p.x, gx0), Ly = fminf(p.y, gy0);
        float Rx = fmaxf(p.z, gx1), Ry = fmaxf(p.w, gy1);
        float ew = fmaxf(Rx - Lx, 0.0f), eh = fmaxf(Ry - Ly, 0.0f);
        float areaE = ew * eh;
        float giou = iou - (areaE - uni) / areaE;

        float cb = fabsf(nx0 - gx0 / s_gt[jg][10])
                 + fabsf(ny0 - gy0 / s_gt[jg][11])
                 + fabsf(nx1 - gx1 / s_gt[jg][12])
                 + fabsf(ny1 - gy1 / s_gt[jg][13]);

        float cc = g_tab[((size_t)b * Cn + s_lab[jg]) * Qn + q];

        float ct = fabsf(ps0 - s_gt[jg][4]) + fabsf(ps1 - s_gt[jg][5]) + fabsf(ps2 - s_gt[jg][6]);
        float cr = fabsf(ps3 - s_gt[jg][7]) + fabsf(ps4 - s_gt[jg][8]) + fabsf(ps5 - s_gt[jg][9]);

        float gcx = (gx0 + gx1) * 0.5f, gcy = (gy0 + gy1) * 0.5f;
        float gw = gx1 - gx0, gh = gy1 - gy0;
        float x0 = gcx - gw * 0.5f, y0 = gcy - gh * 0.5f;
        float x1 = gcx + gw * 0.5f, y1 = gcy + gh * 0.5f;
        bool in_box = (ax > x0) && (ax < x1) && (ay > y0) && (ay < y1);
        float w = x1 - x0, h = y1 - y0;
        bool in_ctr = (ax > gcx - 2.5f * w) && (ax < gcx + 2.5f * w) &&
                      (ay > gcy - 2.5f * h) && (ay < gcy + 2.5f * h);
        bool both = in_box && in_ctr;

        float cost = 5.0f * cb + 2.0f * cc + 2.0f * (-giou)
                   + 100.0f * (both ? 0.0f : 1.0f) + 1.0f * ct + 1.0f * cr + fgpen;

        g_cost[((size_t)b * Gn + g) * Qn + q] = cost;

        // ---- block-level iou top-5 partial for this g ----
        // per-warp 5-round extraction
        int alive = 1;
        for (int r = 0; r < 5; r++) {
            float c = alive ? iou : -INFINITY;
            float m = c;
#pragma unroll
            for (int off = 16; off; off >>= 1) m = fmaxf(m, __shfl_xor_sync(0xffffffffu, m, off));
            unsigned ball = __ballot_sync(0xffffffffu, c == m);
            if (alive && lane == (__ffs(ball) - 1)) alive = 0;
            if (lane == 0) s5w[wrp][r] = m;
        }
        __syncthreads();
        if (wrp == 0) {
            int pr = 0;
            float* dst = g_i5 + (((size_t)b * Gn + g) * NBLK + blockIdx.x) * 5;
            for (int r = 0; r < 5; r++) {
                float c = (lane < 8 && pr < 5) ? s5w[lane][pr] : -INFINITY;
                float m = c;
#pragma unroll
                for (int off = 16; off; off >>= 1) m = fmaxf(m, __shfl_xor_sync(0xffffffffu, m, off));
                unsigned ball = __ballot_sync(0xffffffffu, c == m);
                if (lane == (__ffs(ball) - 1)) pr++;
                if (lane == 0) dst[r] = m;
            }
        }
        __syncthreads();
    }
}

// ---------------- K3: dk from partials (warp per column) ----------------
__global__ void dk_kernel() {
    int wrp = threadIdx.x >> 5, lane = threadIdx.x & 31;
    int g = blockIdx.x * 8 + wrp;
    int b = blockIdx.y;
    const float* src = g_i5 + ((size_t)b * Gn + g) * NBLK * 5;   // 80 floats

    float a0 = src[lane];
    float a1 = src[lane + 32];
    float a2 = (lane < 16) ? src[lane + 64] : -INFINITY;
    // sort descending a0>=a1>=a2
    float t;
    if (a1 > a0) { t = a0; a0 = a1; a1 = t; }
    if (a2 > a1) { t = a1; a1 = a2; a2 = t; }
    if (a1 > a0) { t = a0; a0 = a1; a1 = t; }

    int pr = 0; float sum = 0.0f;
    for (int r = 0; r < 5; r++) {
        float c = (pr == 0) ? a0 : (pr == 1) ? a1 : (pr == 2) ? a2 : -INFINITY;
        float m = c;
#pragma unroll
        for (int off = 16; off; off >>= 1) m = fmaxf(m, __shfl_xor_sync(0xffffffffu, m, off));
        sum += m;
        unsigned ball = __ballot_sync(0xffffffffu, c == m);
        if (lane == (__ffs(ball) - 1)) pr++;
    }
    int dk = (int)sum;
    if (dk < 1) dk = 1;
    if (dk > 5) dk = 5;
    if (lane == 0) g_dk[(size_t)b * Gn + g] = dk;
}

// ---------------- K4: per-column lexicographic cost top-16 (u64 keys) ----------------
__device__ __forceinline__ unsigned long long costKey(float v, int q) {
    unsigned bits = __float_as_uint(v);
    unsigned mk = (bits & 0x80000000u) ? ~bits : (bits ^ 0x80000000u);
    return ((unsigned long long)mk << 32) | (unsigned)q;
}

__global__ void short_kernel() {
    int warp = threadIdx.x >> 5, lane = threadIdx.x & 31;
    int col = blockIdx.x * 4 + warp;
    const float4* c4 = reinterpret_cast<const float4*>(g_cost + (size_t)col * Qn);

    unsigned long long t[Ks];
#pragma unroll
    for (int k = 0; k < Ks; k++) t[k] = ~0ull;

    for (int i = lane; i < Qn / 4; i += 32) {
        float4 v = c4[i];
        int q0 = i * 4;
#pragma unroll
        for (int j = 0; j < 4; j++) {
            float vv = (j == 0) ? v.x : (j == 1) ? v.y : (j == 2) ? v.z : v.w;
            unsigned long long key = costKey(vv, q0 + j);
            if (key < t[Ks - 1]) {
                t[Ks - 1] = key;
#pragma unroll
                for (int k = Ks - 1; k > 0; k--) {
                    unsigned long long a = t[k - 1], bb = t[k];
                    t[k - 1] = (a < bb) ? a : bb;
                    t[k]     = (a < bb) ? bb : a;
                }
            }
        }
    }

    int p = 0;
    int* dst = g_sidx + (size_t)col * Ks;
    for (int r = 0; r < Ks; r++) {
        unsigned long long cand = (p < Ks) ? t[p] : ~0ull;
        unsigned long long m = cand;
#pragma unroll
        for (int off = 16; off; off >>= 1) {
            unsigned long long o = __shfl_xor_sync(0xffffffffu, m, off);
            if (o < m) m = o;
        }
        if (cand == m) {
            p++;
            dst[r] = (int)(m & 0xffffffffu);
        }
    }
}

// ---------------- K5: matching (all shared, no bitmask) ----------------
__global__ void __launch_bounds__(1024, 1) match_kernel(float* __restrict__ out) {
    int b = blockIdx.x, tid = threadIdx.x;
    int wid = tid >> 5, lane = tid & 31;
    const float* Cb = g_cost + (size_t)b * Gn * Qn;
    const int* sidx = g_sidx + (size_t)b * Gn * Ks;

    __shared__ int s_rcnt[Qn];
    __shared__ unsigned char s_pen[Qn];
    __shared__ int s_ming[Qn];
    __shared__ unsigned char s_rg8[Qn];
    __shared__ unsigned s_mat[Qn / 32];
    __shared__ unsigned s_stale[Qn / 32];
    __shared__ int s_col[Gn];
    __shared__ unsigned char s_dk[Gn];
    __shared__ short s_asg[Gn];
    __shared__ unsigned short s_un[Gn], s_fb[Gn];
    __shared__ unsigned short s_slist[1024];
    __shared__ int s_ucnt, s_fbcnt, s_scnt;

    for (int i = tid; i < Qn; i += 1024) { s_rcnt[i] = 0; s_pen[i] = 0; s_ming[i] = 0x7fffffff; }
    for (int i = tid; i < Qn / 32; i += 1024) s_stale[i] = 0u;
    if (tid < Gn) { s_dk[tid] = (unsigned char)g_dk[b * Gn + tid]; s_col[tid] = 0; s_asg[tid] = -1; }
    if (tid == 0) s_scnt = 0;
    __syncthreads();

    if (tid < Gn) {
        int dk = s_dk[tid];
        for (int j = 0; j < dk; j++) atomicAdd(&s_rcnt[sidx[tid * Ks + j]], 1);
    }
    __syncthreads();
    for (int q = tid; q < Qn; q += 1024)
        if (s_rcnt[q] > 1) {
            atomicOr(&s_stale[q >> 5], 1u << (q & 31));
            int k = atomicAdd(&s_scnt, 1);
            if (k < 1024) s_slist[k] = (unsigned short)q;
        }
    __syncthreads();
    int ns = s_scnt; if (ns > 1024) ns = 1024;
    for (int s = wid; s < ns; s += 32) {
        int q = s_slist[s];
        float bv = INFINITY; int bg = 0;
        for (int g = lane; g < Gn; g += 32) {
            float v = Cb[(size_t)g * Qn + q];
            if (v < bv) { bv = v; bg = g; }
        }
        warpMinPair(bv, bg);
        if (lane == 0) s_rg8[q] = (unsigned char)bg;
    }
    __syncthreads();
    for (int q = tid; q < Qn; q += 1024) s_rcnt[q] = 0;
    __syncthreads();
    if (tid < Gn) {
        int dk = s_dk[tid];
        for (int j = 0; j < dk; j++) {
            int q = sidx[tid * Ks + j];
            if (!((s_stale[q >> 5] >> (q & 31)) & 1)) {
                atomicAdd(&s_rcnt[q], 1);
                atomicAdd(&s_col[tid], 1);
                atomicMin(&s_ming[q], tid);
            }
        }
    }
    for (int s = tid; s < ns; s += 1024) {
        int q = s_slist[s];
        int rg = s_rg8[q];
        s_rcnt[q] = 1;
        s_ming[q] = rg;
        atomicAdd(&s_col[rg], 1);
    }
    __syncthreads();

    for (int it = 0; it < Gn; it++) {
        if (tid == 0) { s_ucnt = 0; s_fbcnt = 0; }
        __syncthreads();
        if (tid < Gn && s_col[tid] == 0) {
            int k = atomicAdd(&s_ucnt, 1); s_un[k] = (unsigned short)tid;
        }
        __syncthreads();
        int nu = s_ucnt;
        if (nu == 0) break;
        for (int q = tid; q < Qn; q += 1024) if (s_rcnt[q] > 0) s_pen[q]++;
        if (tid < Qn / 32) {
            unsigned wb = 0;
#pragma unroll 8
            for (int j = 0; j < 32; j++) if (s_rcnt[tid * 32 + j] > 0) wb |= 1u << j;
            s_mat[tid] = wb;
        }
        __syncthreads();
        if (tid < nu) {
            int g = s_un[tid];
            int chosen = -1;
            for (int j = 0; j < Ks; j++) {
                int q = sidx[g * Ks + j];
                if (!((s_mat[q >> 5] >> (q & 31)) & 1)) { chosen = q; break; }
            }
            if (chosen >= 0) {
                atomicAdd(&s_rcnt[chosen], 1);
                atomicMin(&s_ming[chosen], g);
                s_col[g] = 1;
                s_asg[g] = (short)chosen;
            } else {
                int k = atomicAdd(&s_fbcnt, 1); s_fb[k] = (unsigned short)g;
            }
        }
        __syncthreads();
        int nfb = s_fbcnt;
        for (int u = wid; u < nfb; u += 32) {
            int g = s_fb[u];
            const float* col = Cb + (size_t)g * Qn;
            float bv = INFINITY; int bi = 0;
            for (int q = lane; q < Qn; q += 32) {
                if (!((s_mat[q >> 5] >> (q & 31)) & 1)) {
                    float v = col[q];
                    if (v < bv) { bv = v; bi = q; }
                }
            }
            warpMinPair(bv, bi);
            if (bv == INFINITY) {
                bv = INFINITY; bi = 0;
                for (int q = lane; q < Qn; q += 32) {
                    float v = col[q] + 100000.0f * (float)s_pen[q];
                    if (v < bv) { bv = v; bi = q; }
                }
                warpMinPair(bv, bi);
            }
            if (lane == 0) {
                atomicAdd(&s_rcnt[bi], 1);
                atomicMin(&s_ming[bi], g);
                s_col[g] = 1;
                s_asg[g] = (short)bi;
            }
        }
        __syncthreads();
    }

    float* out_sel = out;
    float* out_gt  = out + Bn * Qn;
    float* out_mq  = out + 2 * Bn * Qn;
    for (int q = tid; q < Qn; q += 1024) {
        int r = s_rcnt[q];
        out_sel[(size_t)b * Qn + q] = (r > 0) ? 1.0f : 0.0f;
        out_gt[(size_t)b * Qn + q] = (r > 0) ? (float)s_ming[q] : 0.0f;
    }
    if (tid < Gn) {
        int g = tid;
        const float* col = Cb + (size_t)g * Qn;
        float bv = INFINITY; int bi = 0;
        int dk = s_dk[g];
        for (int j = 0; j < dk; j++) {
            int q = sidx[g * Ks + j];
            if (!((s_stale[q >> 5] >> (q & 31)) & 1)) {
                float v = col[q];
                int p = s_pen[q];
                for (int k = 0; k < p; k++) v += 100000.0f;
                if (v < bv || (v == bv && q < bi)) { bv = v; bi = q; }
            }
        }
        for (int s = 0; s < ns; s++) {
            int q = s_slist[s];
            if (s_rg8[q] == g) {
                float v = col[q];
                int p = s_pen[q];
                for (int k = 0; k < p; k++) v += 100000.0f;
                if (v < bv || (v == bv && q < bi)) { bv = v; bi = q; }
            }
        }
        int aq = s_asg[g];
        if (aq >= 0) {
            float v = col[aq];
            int p = s_pen[aq];
            for (int k = 0; k < p; k++) v += 100000.0f;
            if (v < bv || (v == bv && aq < bi)) { bv = v; bi = aq; }
        }
        out_mq[(size_t)b * Gn + g] = (float)bi;
    }
}

// ---------------- launch ----------------
extern "C" void kernel_launch(void* const* d_in, const int* in_sizes, int n_in,
                              void* d_out, int out_size) {
    const float* pred_logits = (const float*)d_in[0];
    const float* pred_boxes  = (const float*)d_in[1];
    const float* pred_poses  = (const float*)d_in[2];
    const int*   labels      = (const int*)  d_in[3];
    const float* gt_boxes    = (const float*)d_in[4];
    const float* gt_trans    = (const float*)d_in[5];
    const float* gt_rot      = (const float*)d_in[6];
    const float* isz         = (const float*)d_in[7];
    const float* iszt        = (const float*)d_in[8];
    float* out = (float*)d_out;

    probe_kernel<<<1, 32>>>();
    tab_kernel<<<(Bn * Qn + 255) / 256, 256>>>(pred_logits);
    fg_kernel<<<dim3(Qn / 256, Bn), 256>>>(pred_boxes, gt_boxes);
    cost_kernel<<<dim3(Qn / 256, Gn / 8, Bn), 256>>>(pred_boxes, pred_poses, labels,
                                                     gt_boxes, gt_trans, gt_rot, isz, iszt);
    dk_kernel<<<dim3(Gn / 8, Bn), 256>>>();
    short_kernel<<<(Bn * Gn) / 4, 128>>>();
    match_kernel<<<Bn, 1024>>>(out);
}